// round 3
// baseline (speedup 1.0000x reference)
#include <cuda_runtime.h>
#include <cstdint>

#define N_MAX  50000
#define C_IN   128
#define C_HID  128
#define C_OUT  64

// ---------------- scratch (device globals; no allocations) ----------------
__device__ __align__(16) float g_h1  [N_MAX * C_HID];   // x @ W1
__device__ __align__(16) float g_agg1[N_MAX * C_HID];   // aggregated layer-1
__device__ __align__(16) float g_h2  [N_MAX * C_OUT];   // relu(agg1+b1) @ W2
__device__ __align__(16) float g_agg2[N_MAX * C_OUT];   // aggregated layer-2
__device__ float g_dinv[N_MAX];
__device__ int   g_deg [N_MAX];
__device__ float g_weff[C_OUT * C_OUT];   // lin_W[0:64] + lin_W[64:128]
__device__ int   g_is32;                  // 1 if edge_index is int32, 0 if int64

// ---------------- edge index fetch (dtype-agnostic) ----------------
__device__ __forceinline__ int edge_at(const void* ei, long long idx) {
    if (g_is32) return ((const int*)ei)[idx];
    return (int)(((const long long*)ei)[idx]);
}

// ---------------- dtype detector: int64 read out of range => int32 ----------
__global__ void k_detect(const void* __restrict__ ei, int E, int n) {
    __shared__ int bad;
    if (threadIdx.x == 0) bad = 0;
    __syncthreads();
    const long long* p = (const long long*)ei;
    int limit = E < 4096 ? E : 4096;
    for (int i = threadIdx.x; i < limit; i += blockDim.x) {
        long long v = p[i];
        if (v < 0 || v >= (long long)n) bad = 1;
    }
    __syncthreads();
    if (threadIdx.x == 0) g_is32 = bad;   // any violation -> data is int32
}

// ---------------- tiny setup kernels ----------------
__global__ void k_weff(const float* __restrict__ linW) {
    int i = blockIdx.x * blockDim.x + threadIdx.x;
    if (i < C_OUT * C_OUT) g_weff[i] = linW[i] + linW[i + C_OUT * C_OUT];
}

__global__ void k_deg_init(int n) {
    int i = blockIdx.x * blockDim.x + threadIdx.x;
    if (i < n) g_deg[i] = 1;                       // self loop
}

__global__ void k_deg_count(const void* __restrict__ ei, int E, int n) {
    int e = blockIdx.x * blockDim.x + threadIdx.x;
    if (e >= E) return;
    int d = edge_at(ei, (long long)E + e);         // dst row
    if ((unsigned)d < (unsigned)n) atomicAdd(&g_deg[d], 1);
}

__global__ void k_dinv(int n) {
    int i = blockIdx.x * blockDim.x + threadIdx.x;
    if (i < n) g_dinv[i] = rsqrtf((float)g_deg[i]);
}

// ---------------- fp32 GEMM: C[M,N] = op(A[M,128]) @ B[128,N] ----------------
// Block tile: 64 rows x N cols. 256 threads, thread = (tx 0..15, ty 0..15),
// micro-tile 4 rows x (N/16) cols. Optional fused bias+ReLU on the A read.
// a_from_agg1: use g_agg1 as A (ignore Ain). c_sel: 0 -> g_h1, 1 -> g_h2.
template <int N, bool RELU_BIAS>
__global__ void k_gemm(const float* __restrict__ Ain, const float* __restrict__ Bg,
                       const float* __restrict__ bias, int a_from_agg1, int c_sel,
                       int M) {
    const float* A = a_from_agg1 ? g_agg1 : Ain;
    float* C = c_sel ? g_h2 : g_h1;

    constexpr int K = 128, TM = 64, KS = 32;
    constexpr int COLS = N / 16;
    __shared__ float As[TM][KS + 4];
    __shared__ float Bs[KS][N];

    const int tid = threadIdx.x;
    const int tx = tid & 15, ty = tid >> 4;
    const int rowBase = blockIdx.x * TM;

    float acc[4][COLS];
#pragma unroll
    for (int i = 0; i < 4; i++)
#pragma unroll
        for (int j = 0; j < COLS; j++) acc[i][j] = 0.f;

    for (int kb = 0; kb < K; kb += KS) {
        // ---- load A tile: 64 x 32 = 512 float4, 2 per thread
#pragma unroll
        for (int l = 0; l < 2; l++) {
            int idx = tid + l * 256;           // 0..511
            int r   = idx >> 3;
            int k4  = idx & 7;
            int row = rowBase + r;
            float4 v = make_float4(0.f, 0.f, 0.f, 0.f);
            if (row < M)
                v = *(const float4*)(A + (size_t)row * K + kb + k4 * 4);
            if (RELU_BIAS) {
                float4 bv = *(const float4*)(bias + kb + k4 * 4);
                v.x = fmaxf(v.x + bv.x, 0.f);
                v.y = fmaxf(v.y + bv.y, 0.f);
                v.z = fmaxf(v.z + bv.z, 0.f);
                v.w = fmaxf(v.w + bv.w, 0.f);
            }
            As[r][k4 * 4 + 0] = v.x;
            As[r][k4 * 4 + 1] = v.y;
            As[r][k4 * 4 + 2] = v.z;
            As[r][k4 * 4 + 3] = v.w;
        }
        // ---- load B tile: KS x N floats
        constexpr int NB4 = KS * N / 4;
#pragma unroll
        for (int l = 0; l < NB4 / 256; l++) {
            int idx = tid + l * 256;
            int kr  = idx / (N / 4);
            int c4  = idx % (N / 4);
            float4 v = *(const float4*)(Bg + (size_t)(kb + kr) * N + c4 * 4);
            *(float4*)(&Bs[kr][c4 * 4]) = v;
        }
        __syncthreads();

#pragma unroll
        for (int k = 0; k < KS; k++) {
            float a[4];
#pragma unroll
            for (int i = 0; i < 4; i++) a[i] = As[ty * 4 + i][k];
            float b[COLS];
#pragma unroll
            for (int j = 0; j < COLS; j++) b[j] = Bs[k][tx * COLS + j];
#pragma unroll
            for (int i = 0; i < 4; i++)
#pragma unroll
                for (int j = 0; j < COLS; j++) acc[i][j] += a[i] * b[j];
        }
        __syncthreads();
    }

#pragma unroll
    for (int i = 0; i < 4; i++) {
        int row = rowBase + ty * 4 + i;
        if (row < M) {
#pragma unroll
            for (int j = 0; j < COLS; j += 4)
                *(float4*)(C + (size_t)row * N + tx * COLS + j) =
                    make_float4(acc[i][j], acc[i][j + 1], acc[i][j + 2], acc[i][j + 3]);
        }
    }
}

// ---------------- self-loop init: agg[i] = h[i] * dinv[i]^2 ----------------
// layer: 0 -> (g_h1 -> g_agg1), 1 -> (g_h2 -> g_agg2)
template <int F>
__global__ void k_selfinit(int layer, int n) {
    const float* h = layer ? g_h2 : g_h1;
    float* agg     = layer ? g_agg2 : g_agg1;
    constexpr int F4 = F / 4;
    int idx = blockIdx.x * blockDim.x + threadIdx.x;
    if (idx >= n * F4) return;
    int i = idx / F4;
    float di = g_dinv[i];
    float c = di * di;
    float4 v = ((const float4*)h)[idx];
    v.x *= c; v.y *= c; v.z *= c; v.w *= c;
    ((float4*)agg)[idx] = v;
}

// ---------------- edge scatter: agg[dst] += h[src] * dinv[src]*dinv[dst] ----
template <int F>
__global__ void k_scatter(const void* __restrict__ ei, int layer, int E, int n) {
    const float* h = layer ? g_h2 : g_h1;
    float* agg     = layer ? g_agg2 : g_agg1;
    constexpr int TPE = F / 4;                       // lanes per edge
    long long gid = (long long)blockIdx.x * blockDim.x + threadIdx.x;
    int e = (int)(gid / TPE);
    if (e >= E) return;
    int f4 = (int)(gid % TPE);
    int s = edge_at(ei, e);
    int d = edge_at(ei, (long long)E + e);
    if ((unsigned)s >= (unsigned)n || (unsigned)d >= (unsigned)n) return;
    float c = g_dinv[s] * g_dinv[d];
    float4 v = *(const float4*)(h + (size_t)s * F + (size_t)f4 * 4);
    float* o = agg + (size_t)d * F + (size_t)f4 * 4;
    atomicAdd(o + 0, v.x * c);
    atomicAdd(o + 1, v.y * c);
    atomicAdd(o + 2, v.z * c);
    atomicAdd(o + 3, v.w * c);
}

// ---------------- final: (agg2+b2) @ W_eff + lin_b -> log_softmax ----------
__global__ void k_final(const float* __restrict__ b2, const float* __restrict__ linb,
                        float* __restrict__ out, int n) {
    __shared__ float W[C_OUT * C_OUT];
    for (int i = threadIdx.x; i < C_OUT * C_OUT; i += blockDim.x) W[i] = g_weff[i];
    __syncthreads();

    const int lane = threadIdx.x & 31;
    const int warp = threadIdx.x >> 5;
    const int nwarps = blockDim.x >> 5;
    int node = blockIdx.x * nwarps + warp;
    if (node >= n) return;

    const float* a = g_agg2 + (size_t)node * C_OUT;
    float acc0 = linb[lane];
    float acc1 = linb[lane + 32];
#pragma unroll
    for (int k = 0; k < C_OUT; k++) {
        float v = a[k] + b2[k];                     // broadcast load
        acc0 += v * W[k * C_OUT + lane];
        acc1 += v * W[k * C_OUT + lane + 32];
    }
    // warp log-softmax over 64 logits (2 per lane)
    float m = fmaxf(acc0, acc1);
#pragma unroll
    for (int off = 16; off; off >>= 1) m = fmaxf(m, __shfl_xor_sync(0xffffffffu, m, off));
    float s = expf(acc0 - m) + expf(acc1 - m);
#pragma unroll
    for (int off = 16; off; off >>= 1) s += __shfl_xor_sync(0xffffffffu, s, off);
    float lse = m + logf(s);
    out[(size_t)node * C_OUT + lane]      = acc0 - lse;
    out[(size_t)node * C_OUT + lane + 32] = acc1 - lse;
}

// ---------------- launcher ----------------
extern "C" void kernel_launch(void* const* d_in, const int* in_sizes, int n_in,
                              void* d_out, int out_size) {
    const float* x    = (const float*)d_in[0];
    const void*  ei   = d_in[1];                 // int32 OR int64 (detected on device)
    const float* W1   = (const float*)d_in[2];
    const float* b1   = (const float*)d_in[3];
    const float* W2   = (const float*)d_in[4];
    const float* b2   = (const float*)d_in[5];
    const float* linW = (const float*)d_in[6];
    const float* linb = (const float*)d_in[7];
    float* out = (float*)d_out;

    const int n = in_sizes[0] / C_IN;
    const int E = in_sizes[1] / 2;

    // dtype detection + setup
    k_detect<<<1, 256>>>(ei, E, n);
    k_weff<<<(C_OUT * C_OUT + 255) / 256, 256>>>(linW);
    k_deg_init<<<(n + 255) / 256, 256>>>(n);
    k_deg_count<<<(E + 255) / 256, 256>>>(ei, E, n);
    k_dinv<<<(n + 255) / 256, 256>>>(n);

    // layer 1: h1 = x @ W1 ; agg1 = norm-aggregate(h1)
    k_gemm<C_HID, false><<<(n + 63) / 64, 256>>>(x, W1, nullptr, 0, 0, n);
    k_selfinit<C_HID><<<(n * (C_HID / 4) + 255) / 256, 256>>>(0, n);
    {
        long long threads = (long long)E * (C_HID / 4);
        k_scatter<C_HID><<<(int)((threads + 255) / 256), 256>>>(ei, 0, E, n);
    }

    // layer 2: h2 = relu(agg1+b1) @ W2 ; agg2 = norm-aggregate(h2)
    k_gemm<C_OUT, true><<<(n + 63) / 64, 256>>>(nullptr, W2, b1, 1, 1, n);
    k_selfinit<C_OUT><<<(n * (C_OUT / 4) + 255) / 256, 256>>>(1, n);
    {
        long long threads = (long long)E * (C_OUT / 4);
        k_scatter<C_OUT><<<(int)((threads + 255) / 256), 256>>>(ei, 1, E, n);
    }

    // fused output: linear (folded concat) + log_softmax
    k_final<<<(n + 15) / 16, 512>>>(b2, linb, out, n);
}

// round 4
// speedup vs baseline: 1.6653x; 1.6653x over previous
#include <cuda_runtime.h>
#include <cstdint>

#define N_MAX  50000
#define E_MAX  1000000
#define C_IN   128
#define C_HID  128
#define C_OUT  64

// ---------------- scratch (device globals; no allocations) ----------------
__device__ __align__(16) float g_h1  [N_MAX * C_HID];   // (x @ W1) * dinv[row]
__device__ __align__(16) float g_agg1[N_MAX * C_HID];   // aggregated layer-1
__device__ __align__(16) float g_h2  [N_MAX * C_OUT];   // (relu(agg1+b1) @ W2) * dinv[row]
__device__ __align__(16) float g_agg2[N_MAX * C_OUT];   // aggregated layer-2
__device__ float g_dinv[N_MAX];
__device__ int   g_indeg[N_MAX];          // edge in-degree (no self loop)
__device__ int   g_cursor[N_MAX];
__device__ int   g_rowstart[N_MAX + 1];   // CSR (by dst) offsets
__device__ int   g_csrc[E_MAX];           // CSR src ids
__device__ float g_weff[C_OUT * C_OUT];   // lin_W[0:64] + lin_W[64:128]
__device__ int   g_is32;                  // 1 if edge_index is int32

// ---------------- edge index fetch (dtype-agnostic) ----------------
__device__ __forceinline__ int edge_at(const void* ei, long long idx) {
    if (g_is32) return ((const int*)ei)[idx];
    return (int)(((const long long*)ei)[idx]);
}

// ---------------- dtype detector: int64 read out of range => int32 ----------
__global__ void k_detect(const void* __restrict__ ei, int E, int n) {
    __shared__ int bad;
    if (threadIdx.x == 0) bad = 0;
    __syncthreads();
    const long long* p = (const long long*)ei;
    int limit = E < 4096 ? E : 4096;
    for (int i = threadIdx.x; i < limit; i += blockDim.x) {
        long long v = p[i];
        if (v < 0 || v >= (long long)n) bad = 1;
    }
    __syncthreads();
    if (threadIdx.x == 0) g_is32 = bad;
}

// ---------------- tiny setup kernels ----------------
__global__ void k_weff(const float* __restrict__ linW) {
    int i = blockIdx.x * blockDim.x + threadIdx.x;
    if (i < C_OUT * C_OUT) g_weff[i] = linW[i] + linW[i + C_OUT * C_OUT];
}

__global__ void k_zero(int n) {
    int i = blockIdx.x * blockDim.x + threadIdx.x;
    if (i < n) { g_indeg[i] = 0; g_cursor[i] = 0; }
}

__global__ void k_deg_count(const void* __restrict__ ei, int E, int n) {
    int e = blockIdx.x * blockDim.x + threadIdx.x;
    if (e >= E) return;
    int d = edge_at(ei, (long long)E + e);
    if ((unsigned)d < (unsigned)n) atomicAdd(&g_indeg[d], 1);
}

__global__ void k_dinv(int n) {
    int i = blockIdx.x * blockDim.x + threadIdx.x;
    if (i < n) g_dinv[i] = rsqrtf((float)(g_indeg[i] + 1));   // +1 self loop
}

// ---------------- single-block 2-level exclusive scan over indeg ----------
__global__ void k_scan(int n) {
    __shared__ int sums[1024];
    const int tid = threadIdx.x;
    const int chunk = (n + 1023) / 1024;
    const int start = tid * chunk;
    const int end = min(start + chunk, n);
    int s = 0;
    for (int i = start; i < end; i++) s += g_indeg[i];
    sums[tid] = s;
    __syncthreads();
    // Hillis-Steele inclusive scan
    for (int off = 1; off < 1024; off <<= 1) {
        int v = (tid >= off) ? sums[tid - off] : 0;
        __syncthreads();
        sums[tid] += v;
        __syncthreads();
    }
    int base = tid ? sums[tid - 1] : 0;
    for (int i = start; i < end; i++) {
        g_rowstart[i] = base;
        base += g_indeg[i];
    }
    if (tid == 1023) g_rowstart[n] = sums[1023];
}

// ---------------- CSR fill (counting-sort scatter of src ids) --------------
__global__ void k_fill(const void* __restrict__ ei, int E, int n) {
    int e = blockIdx.x * blockDim.x + threadIdx.x;
    if (e >= E) return;
    int s = edge_at(ei, e);
    int d = edge_at(ei, (long long)E + e);
    if ((unsigned)s >= (unsigned)n || (unsigned)d >= (unsigned)n) return;
    int pos = atomicAdd(&g_cursor[d], 1);
    int idx = g_rowstart[d] + pos;
    if (idx < E_MAX) g_csrc[idx] = s;
}

// ---------------- fp32 GEMM: C[M,N] = (op A[M,128]) @ B[128,N], row-scaled --
// Block tile 64 x N, 256 threads, micro-tile 4 x (N/16).
// RELU_BIAS fuses relu(a+bias) on the A read. Epilogue scales row i by dinv[i].
// a_from_agg1: A = g_agg1 (ignore Ain). c_sel: 0 -> g_h1, 1 -> g_h2.
template <int N, bool RELU_BIAS>
__global__ void k_gemm(const float* __restrict__ Ain, const float* __restrict__ Bg,
                       const float* __restrict__ bias, int a_from_agg1, int c_sel,
                       int M) {
    const float* A = a_from_agg1 ? g_agg1 : Ain;
    float* C = c_sel ? g_h2 : g_h1;

    constexpr int K = 128, TM = 64, KS = 32;
    constexpr int COLS = N / 16;
    __shared__ float As[TM][KS + 4];
    __shared__ float Bs[KS][N];

    const int tid = threadIdx.x;
    const int tx = tid & 15, ty = tid >> 4;
    const int rowBase = blockIdx.x * TM;

    float acc[4][COLS];
#pragma unroll
    for (int i = 0; i < 4; i++)
#pragma unroll
        for (int j = 0; j < COLS; j++) acc[i][j] = 0.f;

    for (int kb = 0; kb < K; kb += KS) {
#pragma unroll
        for (int l = 0; l < 2; l++) {
            int idx = tid + l * 256;
            int r   = idx >> 3;
            int k4  = idx & 7;
            int row = rowBase + r;
            float4 v = make_float4(0.f, 0.f, 0.f, 0.f);
            if (row < M)
                v = *(const float4*)(A + (size_t)row * K + kb + k4 * 4);
            if (RELU_BIAS) {
                float4 bv = *(const float4*)(bias + kb + k4 * 4);
                v.x = fmaxf(v.x + bv.x, 0.f);
                v.y = fmaxf(v.y + bv.y, 0.f);
                v.z = fmaxf(v.z + bv.z, 0.f);
                v.w = fmaxf(v.w + bv.w, 0.f);
            }
            As[r][k4 * 4 + 0] = v.x;
            As[r][k4 * 4 + 1] = v.y;
            As[r][k4 * 4 + 2] = v.z;
            As[r][k4 * 4 + 3] = v.w;
        }
        constexpr int NB4 = KS * N / 4;
#pragma unroll
        for (int l = 0; l < NB4 / 256; l++) {
            int idx = tid + l * 256;
            int kr  = idx / (N / 4);
            int c4  = idx % (N / 4);
            float4 v = *(const float4*)(Bg + (size_t)(kb + kr) * N + c4 * 4);
            *(float4*)(&Bs[kr][c4 * 4]) = v;
        }
        __syncthreads();

#pragma unroll
        for (int k = 0; k < KS; k++) {
            float a[4];
#pragma unroll
            for (int i = 0; i < 4; i++) a[i] = As[ty * 4 + i][k];
            float b[COLS];
#pragma unroll
            for (int j = 0; j < COLS; j++) b[j] = Bs[k][tx * COLS + j];
#pragma unroll
            for (int i = 0; i < 4; i++)
#pragma unroll
                for (int j = 0; j < COLS; j++) acc[i][j] += a[i] * b[j];
        }
        __syncthreads();
    }

#pragma unroll
    for (int i = 0; i < 4; i++) {
        int row = rowBase + ty * 4 + i;
        if (row < M) {
            float sc = g_dinv[row];
#pragma unroll
            for (int j = 0; j < COLS; j += 4)
                *(float4*)(C + (size_t)row * N + tx * COLS + j) =
                    make_float4(acc[i][j] * sc, acc[i][j + 1] * sc,
                                acc[i][j + 2] * sc, acc[i][j + 3] * sc);
        }
    }
}

// ---------------- CSR aggregation (warp per node, no atomics) --------------
// h is pre-scaled by dinv[src]; agg[d] = dinv[d] * (h[d] + sum_{e->d} h[src]).
__global__ void k_agg128(int layer_unused, int n) {
    const int lane = threadIdx.x & 31;
    const int warp = threadIdx.x >> 5;
    int node = blockIdx.x * (blockDim.x >> 5) + warp;
    if (node >= n) return;
    const float* h = g_h1;
    float4 acc = *(const float4*)(h + (size_t)node * C_HID + lane * 4);  // self
    int e = g_rowstart[node], end = g_rowstart[node + 1];
    for (; e + 1 < end; e += 2) {
        int s0 = g_csrc[e], s1 = g_csrc[e + 1];
        float4 v0 = *(const float4*)(h + (size_t)s0 * C_HID + lane * 4);
        float4 v1 = *(const float4*)(h + (size_t)s1 * C_HID + lane * 4);
        acc.x += v0.x + v1.x; acc.y += v0.y + v1.y;
        acc.z += v0.z + v1.z; acc.w += v0.w + v1.w;
    }
    if (e < end) {
        int s0 = g_csrc[e];
        float4 v0 = *(const float4*)(h + (size_t)s0 * C_HID + lane * 4);
        acc.x += v0.x; acc.y += v0.y; acc.z += v0.z; acc.w += v0.w;
    }
    float dd = g_dinv[node];
    acc.x *= dd; acc.y *= dd; acc.z *= dd; acc.w *= dd;
    *(float4*)(g_agg1 + (size_t)node * C_HID + lane * 4) = acc;
}

__global__ void k_agg64(int layer_unused, int n) {
    const int lane = threadIdx.x & 31;
    const int warp = threadIdx.x >> 5;
    int node = blockIdx.x * (blockDim.x >> 5) + warp;
    if (node >= n) return;
    const float* h = g_h2;
    float2 acc = *(const float2*)(h + (size_t)node * C_OUT + lane * 2);  // self
    int e = g_rowstart[node], end = g_rowstart[node + 1];
    for (; e + 1 < end; e += 2) {
        int s0 = g_csrc[e], s1 = g_csrc[e + 1];
        float2 v0 = *(const float2*)(h + (size_t)s0 * C_OUT + lane * 2);
        float2 v1 = *(const float2*)(h + (size_t)s1 * C_OUT + lane * 2);
        acc.x += v0.x + v1.x; acc.y += v0.y + v1.y;
    }
    if (e < end) {
        int s0 = g_csrc[e];
        float2 v0 = *(const float2*)(h + (size_t)s0 * C_OUT + lane * 2);
        acc.x += v0.x; acc.y += v0.y;
    }
    float dd = g_dinv[node];
    acc.x *= dd; acc.y *= dd;
    *(float2*)(g_agg2 + (size_t)node * C_OUT + lane * 2) = acc;
}

// ---------------- final: (agg2+b2) @ W_eff + lin_b -> log_softmax ----------
__global__ void k_final(const float* __restrict__ b2, const float* __restrict__ linb,
                        float* __restrict__ out, int n) {
    __shared__ float W[C_OUT * C_OUT];
    for (int i = threadIdx.x; i < C_OUT * C_OUT; i += blockDim.x) W[i] = g_weff[i];
    __syncthreads();

    const int lane = threadIdx.x & 31;
    const int warp = threadIdx.x >> 5;
    const int nwarps = blockDim.x >> 5;
    int node = blockIdx.x * nwarps + warp;
    if (node >= n) return;

    const float* a = g_agg2 + (size_t)node * C_OUT;
    float acc0 = linb[lane];
    float acc1 = linb[lane + 32];
#pragma unroll
    for (int k = 0; k < C_OUT; k++) {
        float v = a[k] + b2[k];
        acc0 += v * W[k * C_OUT + lane];
        acc1 += v * W[k * C_OUT + lane + 32];
    }
    float m = fmaxf(acc0, acc1);
#pragma unroll
    for (int off = 16; off; off >>= 1) m = fmaxf(m, __shfl_xor_sync(0xffffffffu, m, off));
    float s = expf(acc0 - m) + expf(acc1 - m);
#pragma unroll
    for (int off = 16; off; off >>= 1) s += __shfl_xor_sync(0xffffffffu, s, off);
    float lse = m + logf(s);
    out[(size_t)node * C_OUT + lane]      = acc0 - lse;
    out[(size_t)node * C_OUT + lane + 32] = acc1 - lse;
}

// ---------------- launcher ----------------
extern "C" void kernel_launch(void* const* d_in, const int* in_sizes, int n_in,
                              void* d_out, int out_size) {
    const float* x    = (const float*)d_in[0];
    const void*  ei   = d_in[1];
    const float* W1   = (const float*)d_in[2];
    const float* b1   = (const float*)d_in[3];
    const float* W2   = (const float*)d_in[4];
    const float* b2   = (const float*)d_in[5];
    const float* linW = (const float*)d_in[6];
    const float* linb = (const float*)d_in[7];
    float* out = (float*)d_out;

    const int n = in_sizes[0] / C_IN;
    const int E = in_sizes[1] / 2;

    // setup + CSR build
    k_detect<<<1, 256>>>(ei, E, n);
    k_weff<<<(C_OUT * C_OUT + 255) / 256, 256>>>(linW);
    k_zero<<<(n + 255) / 256, 256>>>(n);
    k_deg_count<<<(E + 255) / 256, 256>>>(ei, E, n);
    k_dinv<<<(n + 255) / 256, 256>>>(n);
    k_scan<<<1, 1024>>>(n);
    k_fill<<<(E + 255) / 256, 256>>>(ei, E, n);

    // layer 1: h1 = (x @ W1)*dinv ; agg1 = CSR-aggregate
    k_gemm<C_HID, false><<<(n + 63) / 64, 256>>>(x, W1, nullptr, 0, 0, n);
    k_agg128<<<(n + 7) / 8, 256>>>(0, n);

    // layer 2: h2 = (relu(agg1+b1) @ W2)*dinv ; agg2 = CSR-aggregate
    k_gemm<C_OUT, true><<<(n + 63) / 64, 256>>>(nullptr, W2, b1, 1, 1, n);
    k_agg64<<<(n + 7) / 8, 256>>>(1, n);

    // fused output: linear (folded concat) + log_softmax
    k_final<<<(n + 15) / 16, 512>>>(b2, linb, out, n);
}

// round 5
// speedup vs baseline: 2.8584x; 1.7164x over previous
#include <cuda_runtime.h>
#include <cstdint>

#define N_MAX  50000
#define E_MAX  1000000
#define C_IN   128
#define C_HID  128
#define C_OUT  64

// ---------------- scratch (device globals; no allocations) ----------------
__device__ __align__(16) float g_h1  [N_MAX * C_HID];   // (x @ W1) * dinv[row]
__device__ __align__(16) float g_agg1[N_MAX * C_HID];   // aggregated layer-1
__device__ __align__(16) float g_h2  [N_MAX * C_OUT];   // (relu(agg1+b1) @ W2) * dinv[row]
__device__ __align__(16) float g_agg2[N_MAX * C_OUT];   // aggregated layer-2
__device__ float g_dinv[N_MAX];
__device__ int   g_indeg[N_MAX];          // edge in-degree (no self loop)
__device__ int   g_cursor[N_MAX];
__device__ int   g_rowstart[N_MAX + 1];   // CSR (by dst) offsets
__device__ int   g_csrc[E_MAX];           // CSR src ids
__device__ float g_weff[C_OUT * C_OUT];   // lin_W[0:64] + lin_W[64:128]
__device__ int   g_is32;                  // 1 if edge_index is int32

// ---------------- edge index fetch (dtype-agnostic) ----------------
__device__ __forceinline__ int edge_at(const void* ei, long long idx) {
    if (g_is32) return ((const int*)ei)[idx];
    return (int)(((const long long*)ei)[idx]);
}

// ---------------- dtype detector: int64 read out of range => int32 ----------
__global__ void k_detect(const void* __restrict__ ei, int E, int n) {
    __shared__ int bad;
    if (threadIdx.x == 0) bad = 0;
    __syncthreads();
    const long long* p = (const long long*)ei;
    int limit = E < 4096 ? E : 4096;
    for (int i = threadIdx.x; i < limit; i += blockDim.x) {
        long long v = p[i];
        if (v < 0 || v >= (long long)n) bad = 1;
    }
    __syncthreads();
    if (threadIdx.x == 0) g_is32 = bad;
}

// ---------------- init: zero counters + fold concat weights ----------------
__global__ void k_init(const float* __restrict__ linW, int n) {
    int i = blockIdx.x * blockDim.x + threadIdx.x;
    if (i < n) { g_indeg[i] = 0; g_cursor[i] = 0; }
    if (i < C_OUT * C_OUT) g_weff[i] = linW[i] + linW[i + C_OUT * C_OUT];
}

__global__ void k_deg_count(const void* __restrict__ ei, int E, int n) {
    int e = blockIdx.x * blockDim.x + threadIdx.x;
    if (e >= E) return;
    int d = edge_at(ei, (long long)E + e);
    if ((unsigned)d < (unsigned)n) atomicAdd(&g_indeg[d], 1);
}

// -------- single-block 2-level exclusive scan over indeg (+ dinv fold) -----
__global__ void k_scan(int n) {
    __shared__ int sums[1024];
    const int tid = threadIdx.x;
    const int chunk = (n + 1023) / 1024;
    const int start = tid * chunk;
    const int end = min(start + chunk, n);
    int s = 0;
    for (int i = start; i < end; i++) s += g_indeg[i];
    sums[tid] = s;
    __syncthreads();
    for (int off = 1; off < 1024; off <<= 1) {
        int v = (tid >= off) ? sums[tid - off] : 0;
        __syncthreads();
        sums[tid] += v;
        __syncthreads();
    }
    int base = tid ? sums[tid - 1] : 0;
    for (int i = start; i < end; i++) {
        int di = g_indeg[i];
        g_rowstart[i] = base;
        base += di;
        g_dinv[i] = rsqrtf((float)(di + 1));   // +1 self loop
    }
    if (tid == 1023) g_rowstart[n] = sums[1023];
}

// ---------------- CSR fill (counting-sort scatter of src ids) --------------
__global__ void k_fill(const void* __restrict__ ei, int E, int n) {
    int e = blockIdx.x * blockDim.x + threadIdx.x;
    if (e >= E) return;
    int s = edge_at(ei, e);
    int d = edge_at(ei, (long long)E + e);
    if ((unsigned)s >= (unsigned)n || (unsigned)d >= (unsigned)n) return;
    int pos = atomicAdd(&g_cursor[d], 1);
    int idx = g_rowstart[d] + pos;
    if (idx < E_MAX) g_csrc[idx] = s;
}

// ---------------- fp32 GEMM: C[M,N] = (op A[M,128]) @ B[128,N], row-scaled --
// Block tile 128 x N, 256 threads (tx 0..15, ty 0..15), micro-tile 8 x (N/16).
// A tile stored TRANSPOSED in smem so the 8-row fragment is 2x LDS.128.
// RELU_BIAS fuses relu(a+bias) on A read. Epilogue scales row i by dinv[i].
template <int N, bool RELU_BIAS>
__global__ void k_gemm(const float* __restrict__ Ain, const float* __restrict__ Bg,
                       const float* __restrict__ bias, int a_from_agg1, int c_sel,
                       int M) {
    const float* A = a_from_agg1 ? g_agg1 : Ain;
    float* C = c_sel ? g_h2 : g_h1;

    constexpr int K = 128, TM = 128, KS = 16;
    constexpr int COLS = N / 16;                 // 8 (N=128) or 4 (N=64)
    __shared__ float At[KS][TM + 4];             // transposed A tile
    __shared__ float Bs[KS][N];

    const int tid = threadIdx.x;
    const int tx = tid & 15, ty = tid >> 4;
    const int rowBase = blockIdx.x * TM;

    float acc[8][COLS];
#pragma unroll
    for (int i = 0; i < 8; i++)
#pragma unroll
        for (int j = 0; j < COLS; j++) acc[i][j] = 0.f;

    for (int kb = 0; kb < K; kb += KS) {
        // ---- A tile: 128 rows x 16 k = 512 float4, 2 per thread, transpose
#pragma unroll
        for (int l = 0; l < 2; l++) {
            int idx = tid + l * 256;             // 0..511
            int r   = idx >> 2;                  // 0..127
            int k4  = idx & 3;                   // 0..3
            int row = rowBase + r;
            float4 v = make_float4(0.f, 0.f, 0.f, 0.f);
            if (row < M)
                v = *(const float4*)(A + (size_t)row * K + kb + k4 * 4);
            if (RELU_BIAS) {
                float4 bv = *(const float4*)(bias + kb + k4 * 4);
                v.x = fmaxf(v.x + bv.x, 0.f);
                v.y = fmaxf(v.y + bv.y, 0.f);
                v.z = fmaxf(v.z + bv.z, 0.f);
                v.w = fmaxf(v.w + bv.w, 0.f);
            }
            At[k4 * 4 + 0][r] = v.x;
            At[k4 * 4 + 1][r] = v.y;
            At[k4 * 4 + 2][r] = v.z;
            At[k4 * 4 + 3][r] = v.w;
        }
        // ---- B tile: KS x N floats
        constexpr int NB4 = KS * N / 4;          // 512 or 256 float4
#pragma unroll
        for (int l = 0; l < NB4 / 256; l++) {
            int idx = tid + l * 256;
            int kr  = idx / (N / 4);
            int c4  = idx % (N / 4);
            *(float4*)(&Bs[kr][c4 * 4]) =
                *(const float4*)(Bg + (size_t)(kb + kr) * N + c4 * 4);
        }
        __syncthreads();

#pragma unroll
        for (int k = 0; k < KS; k++) {
            float a[8];
            *(float4*)&a[0] = *(const float4*)&At[k][ty * 8];
            *(float4*)&a[4] = *(const float4*)&At[k][ty * 8 + 4];
            float b[COLS];
#pragma unroll
            for (int j = 0; j < COLS; j += 4)
                *(float4*)&b[j] = *(const float4*)&Bs[k][tx * COLS + j];
#pragma unroll
            for (int i = 0; i < 8; i++)
#pragma unroll
                for (int j = 0; j < COLS; j++) acc[i][j] += a[i] * b[j];
        }
        __syncthreads();
    }

#pragma unroll
    for (int i = 0; i < 8; i++) {
        int row = rowBase + ty * 8 + i;
        if (row < M) {
            float sc = g_dinv[row];
#pragma unroll
            for (int j = 0; j < COLS; j += 4)
                *(float4*)(C + (size_t)row * N + tx * COLS + j) =
                    make_float4(acc[i][j] * sc, acc[i][j + 1] * sc,
                                acc[i][j + 2] * sc, acc[i][j + 3] * sc);
        }
    }
}

// ---------------- CSR aggregation (no atomics) -----------------------------
// h is pre-scaled by dinv[src]; agg[d] = dinv[d] * (h[d] + sum_{e->d} h[src]).

// 128 features: warp per node, lane holds float4. Unroll 4 for MLP.
__global__ void k_agg128(int n) {
    const int lane = threadIdx.x & 31;
    const int warp = threadIdx.x >> 5;
    int node = blockIdx.x * (blockDim.x >> 5) + warp;
    if (node >= n) return;
    const float4* __restrict__ hv = (const float4*)g_h1;
    const int* __restrict__ csrc = g_csrc;

    float4 acc = hv[(size_t)node * 32 + lane];   // self (pre-scaled)
    int e = g_rowstart[node], end = g_rowstart[node + 1];
    for (; e + 4 <= end; e += 4) {
        int s0 = csrc[e], s1 = csrc[e + 1], s2 = csrc[e + 2], s3 = csrc[e + 3];
        float4 v0 = hv[(size_t)s0 * 32 + lane];
        float4 v1 = hv[(size_t)s1 * 32 + lane];
        float4 v2 = hv[(size_t)s2 * 32 + lane];
        float4 v3 = hv[(size_t)s3 * 32 + lane];
        acc.x += (v0.x + v1.x) + (v2.x + v3.x);
        acc.y += (v0.y + v1.y) + (v2.y + v3.y);
        acc.z += (v0.z + v1.z) + (v2.z + v3.z);
        acc.w += (v0.w + v1.w) + (v2.w + v3.w);
    }
    for (; e < end; e++) {
        float4 v = hv[(size_t)csrc[e] * 32 + lane];
        acc.x += v.x; acc.y += v.y; acc.z += v.z; acc.w += v.w;
    }
    float dd = g_dinv[node];
    acc.x *= dd; acc.y *= dd; acc.z *= dd; acc.w *= dd;
    ((float4*)g_agg1)[(size_t)node * 32 + lane] = acc;
}

// 64 features: HALF-warp per node, lane16 holds float4 (16*4 = 64 floats).
__global__ void k_agg64(int n) {
    const int lane16 = threadIdx.x & 15;
    const int half = threadIdx.x >> 4;
    int node = blockIdx.x * (blockDim.x >> 4) + half;
    if (node >= n) return;
    const float4* __restrict__ hv = (const float4*)g_h2;
    const int* __restrict__ csrc = g_csrc;

    float4 acc = hv[(size_t)node * 16 + lane16];   // self (pre-scaled)
    int e = g_rowstart[node], end = g_rowstart[node + 1];
    for (; e + 4 <= end; e += 4) {
        int s0 = csrc[e], s1 = csrc[e + 1], s2 = csrc[e + 2], s3 = csrc[e + 3];
        float4 v0 = hv[(size_t)s0 * 16 + lane16];
        float4 v1 = hv[(size_t)s1 * 16 + lane16];
        float4 v2 = hv[(size_t)s2 * 16 + lane16];
        float4 v3 = hv[(size_t)s3 * 16 + lane16];
        acc.x += (v0.x + v1.x) + (v2.x + v3.x);
        acc.y += (v0.y + v1.y) + (v2.y + v3.y);
        acc.z += (v0.z + v1.z) + (v2.z + v3.z);
        acc.w += (v0.w + v1.w) + (v2.w + v3.w);
    }
    for (; e < end; e++) {
        float4 v = hv[(size_t)csrc[e] * 16 + lane16];
        acc.x += v.x; acc.y += v.y; acc.z += v.z; acc.w += v.w;
    }
    float dd = g_dinv[node];
    acc.x *= dd; acc.y *= dd; acc.z *= dd; acc.w *= dd;
    ((float4*)g_agg2)[(size_t)node * 16 + lane16] = acc;
}

// ---------------- final: (agg2+b2) @ W_eff + lin_b -> log_softmax ----------
__global__ void k_final(const float* __restrict__ b2, const float* __restrict__ linb,
                        float* __restrict__ out, int n) {
    __shared__ float W[C_OUT * C_OUT];
    for (int i = threadIdx.x; i < C_OUT * C_OUT; i += blockDim.x) W[i] = g_weff[i];
    __syncthreads();

    const int lane = threadIdx.x & 31;
    const int warp = threadIdx.x >> 5;
    const int nwarps = blockDim.x >> 5;
    int node = blockIdx.x * nwarps + warp;
    if (node >= n) return;

    const float* a = g_agg2 + (size_t)node * C_OUT;
    float acc0 = linb[lane];
    float acc1 = linb[lane + 32];
#pragma unroll
    for (int k = 0; k < C_OUT; k++) {
        float v = a[k] + b2[k];
        acc0 += v * W[k * C_OUT + lane];
        acc1 += v * W[k * C_OUT + lane + 32];
    }
    float m = fmaxf(acc0, acc1);
#pragma unroll
    for (int off = 16; off; off >>= 1) m = fmaxf(m, __shfl_xor_sync(0xffffffffu, m, off));
    float s = expf(acc0 - m) + expf(acc1 - m);
#pragma unroll
    for (int off = 16; off; off >>= 1) s += __shfl_xor_sync(0xffffffffu, s, off);
    float lse = m + logf(s);
    out[(size_t)node * C_OUT + lane]      = acc0 - lse;
    out[(size_t)node * C_OUT + lane + 32] = acc1 - lse;
}

// ---------------- launcher ----------------
extern "C" void kernel_launch(void* const* d_in, const int* in_sizes, int n_in,
                              void* d_out, int out_size) {
    const float* x    = (const float*)d_in[0];
    const void*  ei   = d_in[1];
    const float* W1   = (const float*)d_in[2];
    const float* b1   = (const float*)d_in[3];
    const float* W2   = (const float*)d_in[4];
    const float* b2   = (const float*)d_in[5];
    const float* linW = (const float*)d_in[6];
    const float* linb = (const float*)d_in[7];
    float* out = (float*)d_out;

    const int n = in_sizes[0] / C_IN;
    const int E = in_sizes[1] / 2;

    // setup + CSR build
    k_detect<<<1, 256>>>(ei, E, n);
    {
        int mx = n > C_OUT * C_OUT ? n : C_OUT * C_OUT;
        k_init<<<(mx + 255) / 256, 256>>>(linW, n);
    }
    k_deg_count<<<(E + 255) / 256, 256>>>(ei, E, n);
    k_scan<<<1, 1024>>>(n);
    k_fill<<<(E + 255) / 256, 256>>>(ei, E, n);

    // layer 1: h1 = (x @ W1)*dinv ; agg1 = CSR-aggregate
    k_gemm<C_HID, false><<<(n + 127) / 128, 256>>>(x, W1, nullptr, 0, 0, n);
    k_agg128<<<(n + 7) / 8, 256>>>(n);

    // layer 2: h2 = (relu(agg1+b1) @ W2)*dinv ; agg2 = CSR-aggregate
    k_gemm<C_OUT, true><<<(n + 127) / 128, 256>>>(nullptr, W2, b1, 1, 1, n);
    k_agg64<<<(n + 15) / 16, 256>>>(n);

    // fused output: linear (folded concat) + log_softmax
    k_final<<<(n + 15) / 16, 512>>>(b2, linb, out, n);
}

// round 6
// speedup vs baseline: 3.6852x; 1.2893x over previous
#include <cuda_runtime.h>
#include <cstdint>

#define N_MAX  50000
#define E_MAX  1000000
#define C_IN   128
#define C_HID  128
#define C_OUT  64

#define SCAN_TILE 1024          // elements per scan block

// ---------------- scratch (device globals; no allocations) ----------------
__device__ __align__(16) float g_h1  [N_MAX * C_HID];   // (x @ W1) * dinv[row]
__device__ __align__(16) float g_agg1[N_MAX * C_HID];   // aggregated layer-1
__device__ __align__(16) float g_h2  [N_MAX * C_OUT];   // (relu(agg1+b1) @ W2) * dinv[row]
__device__ __align__(16) float g_agg2[N_MAX * C_OUT];   // aggregated layer-2
__device__ float g_dinv[N_MAX];
__device__ __align__(16) int g_indeg[N_MAX];   // edge in-degree (no self loop)
__device__ int   g_cursor[N_MAX];
__device__ __align__(16) int g_rowstart[N_MAX + 4];  // CSR (by dst) offsets
__device__ int   g_csrc[E_MAX];           // CSR src ids
__device__ int   g_bsum[(N_MAX + SCAN_TILE - 1) / SCAN_TILE + 1];
__device__ int   g_boff[(N_MAX + SCAN_TILE - 1) / SCAN_TILE + 1];
__device__ float g_weff[C_OUT * C_OUT];   // lin_W[0:64] + lin_W[64:128]
__device__ int   g_is32;                  // 1 if edge_index is int32

// ---------------- edge index fetch (dtype-agnostic) ----------------
__device__ __forceinline__ int edge_at(const void* ei, long long idx) {
    if (g_is32) return ((const int*)ei)[idx];
    return (int)(((const long long*)ei)[idx]);
}

// ---------------- dtype detector: int64 read out of range => int32 ----------
__global__ void k_detect(const void* __restrict__ ei, int E, int n) {
    __shared__ int bad;
    if (threadIdx.x == 0) bad = 0;
    __syncthreads();
    const long long* p = (const long long*)ei;
    int limit = E < 4096 ? E : 4096;
    for (int i = threadIdx.x; i < limit; i += blockDim.x) {
        long long v = p[i];
        if (v < 0 || v >= (long long)n) bad = 1;
    }
    __syncthreads();
    if (threadIdx.x == 0) g_is32 = bad;
}

// ---------------- init: zero counters + fold concat weights ----------------
__global__ void k_init(const float* __restrict__ linW, int n) {
    int i = blockIdx.x * blockDim.x + threadIdx.x;
    if (i < n) { g_indeg[i] = 0; g_cursor[i] = 0; }
    if (i < C_OUT * C_OUT) g_weff[i] = linW[i] + linW[i + C_OUT * C_OUT];
}

__global__ void k_deg_count(const void* __restrict__ ei, int E, int n) {
    int e = blockIdx.x * blockDim.x + threadIdx.x;
    if (e >= E) return;
    int d = edge_at(ei, (long long)E + e);
    if ((unsigned)d < (unsigned)n) atomicAdd(&g_indeg[d], 1);
}

// ---------------- 3-kernel grid scan over indeg -----------------------------
// scan1: per-block scan of 1024 elems (4/thread), local-exclusive rowstart,
//        per-block sum, and dinv = rsqrt(indeg+1).
__global__ void k_scan1(int n) {
    __shared__ int wsum[8];
    __shared__ int woff[8];
    const int tid = threadIdx.x;
    const int lane = tid & 31, wid = tid >> 5;
    const int base = blockIdx.x * SCAN_TILE;
    const int i0 = base + tid * 4;

    int4 v = make_int4(0, 0, 0, 0);
    if (i0 + 3 < n) v = *(const int4*)&g_indeg[i0];
    else {
        if (i0 + 0 < n) v.x = g_indeg[i0 + 0];
        if (i0 + 1 < n) v.y = g_indeg[i0 + 1];
        if (i0 + 2 < n) v.z = g_indeg[i0 + 2];
        if (i0 + 3 < n) v.w = g_indeg[i0 + 3];
    }
    int tot = v.x + v.y + v.z + v.w;

    // warp inclusive scan of tot
    int inc = tot;
#pragma unroll
    for (int off = 1; off < 32; off <<= 1) {
        int o = __shfl_up_sync(0xffffffffu, inc, off);
        if (lane >= off) inc += o;
    }
    if (lane == 31) wsum[wid] = inc;
    __syncthreads();
    if (wid == 0) {
        int s = (lane < 8) ? wsum[lane] : 0;
#pragma unroll
        for (int off = 1; off < 8; off <<= 1) {
            int o = __shfl_up_sync(0xffffffffu, s, off);
            if (lane >= off) s += o;
        }
        if (lane < 8) woff[lane] = s - wsum[lane];   // exclusive
        if (lane == 7) g_bsum[blockIdx.x] = s;       // block total
    }
    __syncthreads();

    int excl = woff[wid] + (inc - tot);              // exclusive prefix for i0
    if (i0 + 0 < n) { g_rowstart[i0 + 0] = excl;                     g_dinv[i0 + 0] = rsqrtf((float)(v.x + 1)); }
    if (i0 + 1 < n) { g_rowstart[i0 + 1] = excl + v.x;               g_dinv[i0 + 1] = rsqrtf((float)(v.y + 1)); }
    if (i0 + 2 < n) { g_rowstart[i0 + 2] = excl + v.x + v.y;         g_dinv[i0 + 2] = rsqrtf((float)(v.z + 1)); }
    if (i0 + 3 < n) { g_rowstart[i0 + 3] = excl + v.x + v.y + v.z;   g_dinv[i0 + 3] = rsqrtf((float)(v.w + 1)); }
}

// scan2: single block scans the <=256 block sums (Hillis-Steele in smem).
__global__ void k_scan2(int nb, int n) {
    __shared__ int s[256];
    const int tid = threadIdx.x;
    s[tid] = (tid < nb) ? g_bsum[tid] : 0;
    __syncthreads();
    for (int off = 1; off < 256; off <<= 1) {
        int v = (tid >= off) ? s[tid - off] : 0;
        __syncthreads();
        s[tid] += v;
        __syncthreads();
    }
    if (tid < nb) g_boff[tid] = tid ? s[tid - 1] : 0;   // exclusive
    if (tid == 255) g_rowstart[n] = s[255];             // grand total
}

// scan3: add block offsets.
__global__ void k_scan3(int n) {
    int off = g_boff[blockIdx.x];
    int i0 = blockIdx.x * SCAN_TILE + threadIdx.x * 4;
    if (i0 + 3 < n) {
        int4 r = *(const int4*)&g_rowstart[i0];
        r.x += off; r.y += off; r.z += off; r.w += off;
        *(int4*)&g_rowstart[i0] = r;
    } else {
        for (int j = 0; j < 4 && i0 + j < n; j++) g_rowstart[i0 + j] += off;
    }
}

// ---------------- CSR fill (counting-sort scatter of src ids) --------------
__global__ void k_fill(const void* __restrict__ ei, int E, int n) {
    int e = blockIdx.x * blockDim.x + threadIdx.x;
    if (e >= E) return;
    int s = edge_at(ei, e);
    int d = edge_at(ei, (long long)E + e);
    if ((unsigned)s >= (unsigned)n || (unsigned)d >= (unsigned)n) return;
    int pos = atomicAdd(&g_cursor[d], 1);
    int idx = g_rowstart[d] + pos;
    if (idx < E_MAX) g_csrc[idx] = s;
}

// ---------------- fp32 GEMM: C[M,N] = (op A[M,128]) @ B[128,N], row-scaled --
// Block tile 128 x N, 256 threads (tx 0..15, ty 0..15), micro-tile 8 x (N/16).
// A tile stored TRANSPOSED in smem so the 8-row fragment is 2x LDS.128.
// RELU_BIAS fuses relu(a+bias) on A read. Epilogue scales row i by dinv[i].
template <int N, bool RELU_BIAS>
__global__ void k_gemm(const float* __restrict__ Ain, const float* __restrict__ Bg,
                       const float* __restrict__ bias, int a_from_agg1, int c_sel,
                       int M) {
    const float* A = a_from_agg1 ? g_agg1 : Ain;
    float* C = c_sel ? g_h2 : g_h1;

    constexpr int K = 128, TM = 128, KS = 16;
    constexpr int COLS = N / 16;                 // 8 (N=128) or 4 (N=64)
    __shared__ float At[KS][TM + 4];             // transposed A tile
    __shared__ float Bs[KS][N];

    const int tid = threadIdx.x;
    const int tx = tid & 15, ty = tid >> 4;
    const int rowBase = blockIdx.x * TM;

    float acc[8][COLS];
#pragma unroll
    for (int i = 0; i < 8; i++)
#pragma unroll
        for (int j = 0; j < COLS; j++) acc[i][j] = 0.f;

    for (int kb = 0; kb < K; kb += KS) {
#pragma unroll
        for (int l = 0; l < 2; l++) {
            int idx = tid + l * 256;             // 0..511
            int r   = idx >> 2;                  // 0..127
            int k4  = idx & 3;                   // 0..3
            int row = rowBase + r;
            float4 v = make_float4(0.f, 0.f, 0.f, 0.f);
            if (row < M)
                v = *(const float4*)(A + (size_t)row * K + kb + k4 * 4);
            if (RELU_BIAS) {
                float4 bv = *(const float4*)(bias + kb + k4 * 4);
                v.x = fmaxf(v.x + bv.x, 0.f);
                v.y = fmaxf(v.y + bv.y, 0.f);
                v.z = fmaxf(v.z + bv.z, 0.f);
                v.w = fmaxf(v.w + bv.w, 0.f);
            }
            At[k4 * 4 + 0][r] = v.x;
            At[k4 * 4 + 1][r] = v.y;
            At[k4 * 4 + 2][r] = v.z;
            At[k4 * 4 + 3][r] = v.w;
        }
        constexpr int NB4 = KS * N / 4;          // 512 or 256 float4
#pragma unroll
        for (int l = 0; l < NB4 / 256; l++) {
            int idx = tid + l * 256;
            int kr  = idx / (N / 4);
            int c4  = idx % (N / 4);
            *(float4*)(&Bs[kr][c4 * 4]) =
                *(const float4*)(Bg + (size_t)(kb + kr) * N + c4 * 4);
        }
        __syncthreads();

#pragma unroll
        for (int k = 0; k < KS; k++) {
            float a[8];
            *(float4*)&a[0] = *(const float4*)&At[k][ty * 8];
            *(float4*)&a[4] = *(const float4*)&At[k][ty * 8 + 4];
            float b[COLS];
#pragma unroll
            for (int j = 0; j < COLS; j += 4)
                *(float4*)&b[j] = *(const float4*)&Bs[k][tx * COLS + j];
#pragma unroll
            for (int i = 0; i < 8; i++)
#pragma unroll
                for (int j = 0; j < COLS; j++) acc[i][j] += a[i] * b[j];
        }
        __syncthreads();
    }

#pragma unroll
    for (int i = 0; i < 8; i++) {
        int row = rowBase + ty * 8 + i;
        if (row < M) {
            float sc = g_dinv[row];
#pragma unroll
            for (int j = 0; j < COLS; j += 4)
                *(float4*)(C + (size_t)row * N + tx * COLS + j) =
                    make_float4(acc[i][j] * sc, acc[i][j + 1] * sc,
                                acc[i][j + 2] * sc, acc[i][j + 3] * sc);
        }
    }
}

// ---------------- CSR aggregation (no atomics) -----------------------------
// h is pre-scaled by dinv[src]; agg[d] = dinv[d] * (h[d] + sum_{e->d} h[src]).

// 128 features: warp per node, lane holds float4. Unroll 4 for MLP.
__global__ void k_agg128(int n) {
    const int lane = threadIdx.x & 31;
    const int warp = threadIdx.x >> 5;
    int node = blockIdx.x * (blockDim.x >> 5) + warp;
    if (node >= n) return;
    const float4* __restrict__ hv = (const float4*)g_h1;
    const int* __restrict__ csrc = g_csrc;

    float4 acc = hv[(size_t)node * 32 + lane];   // self (pre-scaled)
    int e = g_rowstart[node], end = g_rowstart[node + 1];
    for (; e + 4 <= end; e += 4) {
        int s0 = csrc[e], s1 = csrc[e + 1], s2 = csrc[e + 2], s3 = csrc[e + 3];
        float4 v0 = hv[(size_t)s0 * 32 + lane];
        float4 v1 = hv[(size_t)s1 * 32 + lane];
        float4 v2 = hv[(size_t)s2 * 32 + lane];
        float4 v3 = hv[(size_t)s3 * 32 + lane];
        acc.x += (v0.x + v1.x) + (v2.x + v3.x);
        acc.y += (v0.y + v1.y) + (v2.y + v3.y);
        acc.z += (v0.z + v1.z) + (v2.z + v3.z);
        acc.w += (v0.w + v1.w) + (v2.w + v3.w);
    }
    for (; e < end; e++) {
        float4 v = hv[(size_t)csrc[e] * 32 + lane];
        acc.x += v.x; acc.y += v.y; acc.z += v.z; acc.w += v.w;
    }
    float dd = g_dinv[node];
    acc.x *= dd; acc.y *= dd; acc.z *= dd; acc.w *= dd;
    ((float4*)g_agg1)[(size_t)node * 32 + lane] = acc;
}

// 64 features: HALF-warp per node, lane16 holds float4 (16*4 = 64 floats).
__global__ void k_agg64(int n) {
    const int lane16 = threadIdx.x & 15;
    const int half = threadIdx.x >> 4;
    int node = blockIdx.x * (blockDim.x >> 4) + half;
    if (node >= n) return;
    const float4* __restrict__ hv = (const float4*)g_h2;
    const int* __restrict__ csrc = g_csrc;

    float4 acc = hv[(size_t)node * 16 + lane16];   // self (pre-scaled)
    int e = g_rowstart[node], end = g_rowstart[node + 1];
    for (; e + 4 <= end; e += 4) {
        int s0 = csrc[e], s1 = csrc[e + 1], s2 = csrc[e + 2], s3 = csrc[e + 3];
        float4 v0 = hv[(size_t)s0 * 16 + lane16];
        float4 v1 = hv[(size_t)s1 * 16 + lane16];
        float4 v2 = hv[(size_t)s2 * 16 + lane16];
        float4 v3 = hv[(size_t)s3 * 16 + lane16];
        acc.x += (v0.x + v1.x) + (v2.x + v3.x);
        acc.y += (v0.y + v1.y) + (v2.y + v3.y);
        acc.z += (v0.z + v1.z) + (v2.z + v3.z);
        acc.w += (v0.w + v1.w) + (v2.w + v3.w);
    }
    for (; e < end; e++) {
        float4 v = hv[(size_t)csrc[e] * 16 + lane16];
        acc.x += v.x; acc.y += v.y; acc.z += v.z; acc.w += v.w;
    }
    float dd = g_dinv[node];
    acc.x *= dd; acc.y *= dd; acc.z *= dd; acc.w *= dd;
    ((float4*)g_agg2)[(size_t)node * 16 + lane16] = acc;
}

// ---------------- final: (agg2+b2) @ W_eff + lin_b -> log_softmax ----------
__global__ void k_final(const float* __restrict__ b2, const float* __restrict__ linb,
                        float* __restrict__ out, int n) {
    __shared__ float W[C_OUT * C_OUT];
    for (int i = threadIdx.x; i < C_OUT * C_OUT; i += blockDim.x) W[i] = g_weff[i];
    __syncthreads();

    const int lane = threadIdx.x & 31;
    const int warp = threadIdx.x >> 5;
    const int nwarps = blockDim.x >> 5;
    int node = blockIdx.x * nwarps + warp;
    if (node >= n) return;

    const float* a = g_agg2 + (size_t)node * C_OUT;
    float acc0 = linb[lane];
    float acc1 = linb[lane + 32];
#pragma unroll
    for (int k = 0; k < C_OUT; k++) {
        float v = a[k] + b2[k];
        acc0 += v * W[k * C_OUT + lane];
        acc1 += v * W[k * C_OUT + lane + 32];
    }
    float m = fmaxf(acc0, acc1);
#pragma unroll
    for (int off = 16; off; off >>= 1) m = fmaxf(m, __shfl_xor_sync(0xffffffffu, m, off));
    float s = expf(acc0 - m) + expf(acc1 - m);
#pragma unroll
    for (int off = 16; off; off >>= 1) s += __shfl_xor_sync(0xffffffffu, s, off);
    float lse = m + logf(s);
    out[(size_t)node * C_OUT + lane]      = acc0 - lse;
    out[(size_t)node * C_OUT + lane + 32] = acc1 - lse;
}

// ---------------- launcher ----------------
extern "C" void kernel_launch(void* const* d_in, const int* in_sizes, int n_in,
                              void* d_out, int out_size) {
    const float* x    = (const float*)d_in[0];
    const void*  ei   = d_in[1];
    const float* W1   = (const float*)d_in[2];
    const float* b1   = (const float*)d_in[3];
    const float* W2   = (const float*)d_in[4];
    const float* b2   = (const float*)d_in[5];
    const float* linW = (const float*)d_in[6];
    const float* linb = (const float*)d_in[7];
    float* out = (float*)d_out;

    const int n = in_sizes[0] / C_IN;
    const int E = in_sizes[1] / 2;
    const int nb = (n + SCAN_TILE - 1) / SCAN_TILE;

    // setup + CSR build
    k_detect<<<1, 256>>>(ei, E, n);
    {
        int mx = n > C_OUT * C_OUT ? n : C_OUT * C_OUT;
        k_init<<<(mx + 255) / 256, 256>>>(linW, n);
    }
    k_deg_count<<<(E + 255) / 256, 256>>>(ei, E, n);
    k_scan1<<<nb, 256>>>(n);
    k_scan2<<<1, 256>>>(nb, n);
    k_scan3<<<nb, 256>>>(n);
    k_fill<<<(E + 255) / 256, 256>>>(ei, E, n);

    // layer 1: h1 = (x @ W1)*dinv ; agg1 = CSR-aggregate
    k_gemm<C_HID, false><<<(n + 127) / 128, 256>>>(x, W1, nullptr, 0, 0, n);
    k_agg128<<<(n + 7) / 8, 256>>>(n);

    // layer 2: h2 = (relu(agg1+b1) @ W2)*dinv ; agg2 = CSR-aggregate
    k_gemm<C_OUT, true><<<(n + 127) / 128, 256>>>(nullptr, W2, b1, 1, 1, n);
    k_agg64<<<(n + 15) / 16, 256>>>(n);

    // fused output: linear (folded concat) + log_softmax
    k_final<<<(n + 15) / 16, 512>>>(b2, linb, out, n);
}

// round 8
// speedup vs baseline: 3.8585x; 1.0470x over previous
#include <cuda_runtime.h>
#include <cuda_bf16.h>
#include <cstdint>

#define N_MAX  50000
#define E_MAX  1000000
#define C_IN   128
#define C_HID  128
#define C_OUT  64

#define SCAN_TILE 1024          // elements per scan block

// ---------------- scratch (device globals; no allocations) ----------------
__device__ __align__(16) float g_h1  [N_MAX * C_HID];   // (x @ W1) * dinv[row]
__device__ __align__(16) float g_agg1[N_MAX * C_HID];   // aggregated layer-1
__device__ __align__(16) float g_h2  [N_MAX * C_OUT];   // (relu(agg1+b1) @ W2) * dinv[row]
__device__ __align__(16) float g_agg2[N_MAX * C_OUT];   // aggregated layer-2
__device__ float g_dinv[N_MAX];
__device__ __align__(16) int g_indeg[N_MAX];   // edge in-degree (no self loop)
__device__ int   g_cursor[N_MAX];
__device__ __align__(16) int g_rowstart[N_MAX + 4];  // CSR (by dst) offsets
__device__ int   g_csrc[E_MAX];           // CSR src ids
__device__ int   g_bsum[(N_MAX + SCAN_TILE - 1) / SCAN_TILE + 1];
__device__ int   g_boff[(N_MAX + SCAN_TILE - 1) / SCAN_TILE + 1];
__device__ float g_weff[C_OUT * C_OUT];   // lin_W[0:64] + lin_W[64:128]
__device__ int   g_is32;                  // 1 if edge_index is int32

// ---------------- edge index fetch (dtype-agnostic) ----------------
__device__ __forceinline__ int edge_at(const void* ei, long long idx) {
    if (g_is32) return ((const int*)ei)[idx];
    return (int)(((const long long*)ei)[idx]);
}

// ---------------- dtype detector: int64 read out of range => int32 ----------
__global__ void k_detect(const void* __restrict__ ei, int E, int n) {
    __shared__ int bad;
    if (threadIdx.x == 0) bad = 0;
    __syncthreads();
    const long long* p = (const long long*)ei;
    int limit = E < 4096 ? E : 4096;
    for (int i = threadIdx.x; i < limit; i += blockDim.x) {
        long long v = p[i];
        if (v < 0 || v >= (long long)n) bad = 1;
    }
    __syncthreads();
    if (threadIdx.x == 0) g_is32 = bad;
}

// ---------------- init: zero counters + fold concat weights ----------------
__global__ void k_init(const float* __restrict__ linW, int n) {
    int i = blockIdx.x * blockDim.x + threadIdx.x;
    if (i < n) { g_indeg[i] = 0; g_cursor[i] = 0; }
    if (i < C_OUT * C_OUT) g_weff[i] = linW[i] + linW[i + C_OUT * C_OUT];
}

__global__ void k_deg_count(const void* __restrict__ ei, int E, int n) {
    int e = blockIdx.x * blockDim.x + threadIdx.x;
    if (e >= E) return;
    int d = edge_at(ei, (long long)E + e);
    if ((unsigned)d < (unsigned)n) atomicAdd(&g_indeg[d], 1);
}

// ---------------- 3-kernel grid scan over indeg -----------------------------
__global__ void k_scan1(int n) {
    __shared__ int wsum[8];
    __shared__ int woff[8];
    const int tid = threadIdx.x;
    const int lane = tid & 31, wid = tid >> 5;
    const int base = blockIdx.x * SCAN_TILE;
    const int i0 = base + tid * 4;

    int4 v = make_int4(0, 0, 0, 0);
    if (i0 + 3 < n) v = *(const int4*)&g_indeg[i0];
    else {
        if (i0 + 0 < n) v.x = g_indeg[i0 + 0];
        if (i0 + 1 < n) v.y = g_indeg[i0 + 1];
        if (i0 + 2 < n) v.z = g_indeg[i0 + 2];
        if (i0 + 3 < n) v.w = g_indeg[i0 + 3];
    }
    int tot = v.x + v.y + v.z + v.w;

    int inc = tot;
#pragma unroll
    for (int off = 1; off < 32; off <<= 1) {
        int o = __shfl_up_sync(0xffffffffu, inc, off);
        if (lane >= off) inc += o;
    }
    if (lane == 31) wsum[wid] = inc;
    __syncthreads();
    if (wid == 0) {
        int s = (lane < 8) ? wsum[lane] : 0;
#pragma unroll
        for (int off = 1; off < 8; off <<= 1) {
            int o = __shfl_up_sync(0xffffffffu, s, off);
            if (lane >= off) s += o;
        }
        if (lane < 8) woff[lane] = s - wsum[lane];
        if (lane == 7) g_bsum[blockIdx.x] = s;
    }
    __syncthreads();

    int excl = woff[wid] + (inc - tot);
    if (i0 + 0 < n) { g_rowstart[i0 + 0] = excl;                     g_dinv[i0 + 0] = rsqrtf((float)(v.x + 1)); }
    if (i0 + 1 < n) { g_rowstart[i0 + 1] = excl + v.x;               g_dinv[i0 + 1] = rsqrtf((float)(v.y + 1)); }
    if (i0 + 2 < n) { g_rowstart[i0 + 2] = excl + v.x + v.y;         g_dinv[i0 + 2] = rsqrtf((float)(v.z + 1)); }
    if (i0 + 3 < n) { g_rowstart[i0 + 3] = excl + v.x + v.y + v.z;   g_dinv[i0 + 3] = rsqrtf((float)(v.w + 1)); }
}

__global__ void k_scan2(int nb, int n) {
    __shared__ int s[256];
    const int tid = threadIdx.x;
    s[tid] = (tid < nb) ? g_bsum[tid] : 0;
    __syncthreads();
    for (int off = 1; off < 256; off <<= 1) {
        int v = (tid >= off) ? s[tid - off] : 0;
        __syncthreads();
        s[tid] += v;
        __syncthreads();
    }
    if (tid < nb) g_boff[tid] = tid ? s[tid - 1] : 0;
    if (tid == 255) g_rowstart[n] = s[255];
}

__global__ void k_scan3(int n) {
    int off = g_boff[blockIdx.x];
    int i0 = blockIdx.x * SCAN_TILE + threadIdx.x * 4;
    if (i0 + 3 < n) {
        int4 r = *(const int4*)&g_rowstart[i0];
        r.x += off; r.y += off; r.z += off; r.w += off;
        *(int4*)&g_rowstart[i0] = r;
    } else {
        for (int j = 0; j < 4 && i0 + j < n; j++) g_rowstart[i0 + j] += off;
    }
}

// ---------------- CSR fill (counting-sort scatter of src ids) --------------
__global__ void k_fill(const void* __restrict__ ei, int E, int n) {
    int e = blockIdx.x * blockDim.x + threadIdx.x;
    if (e >= E) return;
    int s = edge_at(ei, e);
    int d = edge_at(ei, (long long)E + e);
    if ((unsigned)s >= (unsigned)n || (unsigned)d >= (unsigned)n) return;
    int pos = atomicAdd(&g_cursor[d], 1);
    int idx = g_rowstart[d] + pos;
    if (idx < E_MAX) g_csrc[idx] = s;
}

// ============ bf16x3 tensor-core GEMM via mma.sync (m16n8k16) ==============
// C[M,N] = (op A[M,128]) @ B[128,N], epilogue scales row i by dinv[i].
// A = Ah + Al, B = Bh + Bl (bf16 splits); D = Ah*Bh + Ah*Bl + Al*Bh (fp32 acc).
// CTA: 256 threads = 8 warps x 16 rows = 128-row tile.
// B staged per K-half (64) in smem as bf16x2 pairs, row stride N+8 so the
// fragment-load bank index is (8q + g) mod 32 — conflict-free.

__device__ __forceinline__ uint32_t pack_hi(float x, float y) {
    __nv_bfloat16 a = __float2bfloat16(x), b = __float2bfloat16(y);
    return ((uint32_t)__bfloat16_as_ushort(b) << 16) | __bfloat16_as_ushort(a);
}
__device__ __forceinline__ uint32_t pack_lo(float x, float y) {
    __nv_bfloat16 a = __float2bfloat16(x), b = __float2bfloat16(y);
    float rx = x - __bfloat162float(a), ry = y - __bfloat162float(b);
    __nv_bfloat16 c = __float2bfloat16(rx), d = __float2bfloat16(ry);
    return ((uint32_t)__bfloat16_as_ushort(d) << 16) | __bfloat16_as_ushort(c);
}

__device__ __forceinline__ void mma_bf16(float* d, uint32_t a0, uint32_t a1,
                                         uint32_t a2, uint32_t a3,
                                         uint32_t b0, uint32_t b1) {
    asm volatile(
        "mma.sync.aligned.m16n8k16.row.col.f32.bf16.bf16.f32 "
        "{%0,%1,%2,%3}, {%4,%5,%6,%7}, {%8,%9}, {%0,%1,%2,%3};"
        : "+f"(d[0]), "+f"(d[1]), "+f"(d[2]), "+f"(d[3])
        : "r"(a0), "r"(a1), "r"(a2), "r"(a3), "r"(b0), "r"(b1));
}

template <int N, bool RELU_BIAS>
__global__ void __launch_bounds__(256)
k_gemm_mma(const float* __restrict__ Ain, const float* __restrict__ Bg,
           const float* __restrict__ bias, int a_from_agg1, int c_sel, int M) {
    constexpr int LD = N + 8;                 // pad: conflict-free frag loads
    constexpr int NT = N / 8;                 // n-tiles per warp row-tile
    __shared__ uint32_t sBh[32][LD];          // bf16x2 pairs, K-half staged
    __shared__ uint32_t sBl[32][LD];

    const float* A = a_from_agg1 ? g_agg1 : Ain;
    float* C = c_sel ? g_h2 : g_h1;

    const int tid = threadIdx.x;
    const int warp = tid >> 5, lane = tid & 31;
    const int g = lane >> 2, q = lane & 3;
    const int row0 = blockIdx.x * 128 + warp * 16 + g;
    const int row1 = row0 + 8;
    const bool v0 = row0 < M, v1 = row1 < M;

    float acc[NT][4];
#pragma unroll
    for (int c = 0; c < NT; c++)
#pragma unroll
        for (int i = 0; i < 4; i++) acc[c][i] = 0.f;

    const float* ar0 = A + (size_t)row0 * 128;
    const float* ar1 = A + (size_t)row1 * 128;

    for (int half = 0; half < 2; half++) {
        __syncthreads();                      // protect previous half's tiles
        // ---- stage B[half*64 + k][n] as bf16x2 (kp = k/2, low half = even k)
        for (int idx = tid; idx < 64 * N; idx += 256) {
            int k = idx / N;
            int nn = idx - k * N;
            float v = Bg[(size_t)(half * 64 + k) * N + nn];
            __nv_bfloat16 hi = __float2bfloat16(v);
            __nv_bfloat16 lo = __float2bfloat16(v - __bfloat162float(hi));
            ((unsigned short*)&sBh[k >> 1][nn])[k & 1] = __bfloat16_as_ushort(hi);
            ((unsigned short*)&sBl[k >> 1][nn])[k & 1] = __bfloat16_as_ushort(lo);
        }
        __syncthreads();

#pragma unroll
        for (int j = 0; j < 4; j++) {
            const int kb = half * 64 + j * 16;
            // ---- A fragments (documented m16n8k16 mapping)
            float2 p00 = make_float2(0.f, 0.f), p01 = p00, p10 = p00, p11 = p00;
            if (v0) { p00 = *(const float2*)(ar0 + kb + 2 * q);
                      p01 = *(const float2*)(ar0 + kb + 2 * q + 8); }
            if (v1) { p10 = *(const float2*)(ar1 + kb + 2 * q);
                      p11 = *(const float2*)(ar1 + kb + 2 * q + 8); }
            if (RELU_BIAS) {
                float2 bA = *(const float2*)(bias + kb + 2 * q);
                float2 bB = *(const float2*)(bias + kb + 2 * q + 8);
                p00.x = fmaxf(p00.x + bA.x, 0.f); p00.y = fmaxf(p00.y + bA.y, 0.f);
                p01.x = fmaxf(p01.x + bB.x, 0.f); p01.y = fmaxf(p01.y + bB.y, 0.f);
                p10.x = fmaxf(p10.x + bA.x, 0.f); p10.y = fmaxf(p10.y + bA.y, 0.f);
                p11.x = fmaxf(p11.x + bB.x, 0.f); p11.y = fmaxf(p11.y + bB.y, 0.f);
            }
            uint32_t ah0 = pack_hi(p00.x, p00.y), al0 = pack_lo(p00.x, p00.y);
            uint32_t ah1 = pack_hi(p10.x, p10.y), al1 = pack_lo(p10.x, p10.y);
            uint32_t ah2 = pack_hi(p01.x, p01.y), al2 = pack_lo(p01.x, p01.y);
            uint32_t ah3 = pack_hi(p11.x, p11.y), al3 = pack_lo(p11.x, p11.y);

            const int kp0 = j * 8 + q, kp1 = kp0 + 4;
#pragma unroll
            for (int c = 0; c < NT; c++) {
                int nn = c * 8 + g;
                uint32_t b0h = sBh[kp0][nn];
                uint32_t b1h = sBh[kp1][nn];
                uint32_t b0l = sBl[kp0][nn];
                uint32_t b1l = sBl[kp1][nn];
                mma_bf16(acc[c], ah0, ah1, ah2, ah3, b0h, b1h);
                mma_bf16(acc[c], ah0, ah1, ah2, ah3, b0l, b1l);
                mma_bf16(acc[c], al0, al1, al2, al3, b0h, b1h);
            }
        }
    }

    // ---- epilogue: dinv row scale, float2 stores
    float s0 = v0 ? g_dinv[row0] : 0.f;
    float s1 = v1 ? g_dinv[row1] : 0.f;
#pragma unroll
    for (int c = 0; c < NT; c++) {
        int col = c * 8 + 2 * q;
        if (v0) *(float2*)(C + (size_t)row0 * N + col) =
            make_float2(acc[c][0] * s0, acc[c][1] * s0);
        if (v1) *(float2*)(C + (size_t)row1 * N + col) =
            make_float2(acc[c][2] * s1, acc[c][3] * s1);
    }
}

// ---------------- CSR aggregation (no atomics) -----------------------------
__global__ void k_agg128(int n) {
    const int lane = threadIdx.x & 31;
    const int warp = threadIdx.x >> 5;
    int node = blockIdx.x * (blockDim.x >> 5) + warp;
    if (node >= n) return;
    const float4* __restrict__ hv = (const float4*)g_h1;
    const int* __restrict__ csrc = g_csrc;

    float4 acc = hv[(size_t)node * 32 + lane];
    int e = g_rowstart[node], end = g_rowstart[node + 1];
    for (; e + 4 <= end; e += 4) {
        int s0 = csrc[e], s1 = csrc[e + 1], s2 = csrc[e + 2], s3 = csrc[e + 3];
        float4 v0 = hv[(size_t)s0 * 32 + lane];
        float4 v1 = hv[(size_t)s1 * 32 + lane];
        float4 v2 = hv[(size_t)s2 * 32 + lane];
        float4 v3 = hv[(size_t)s3 * 32 + lane];
        acc.x += (v0.x + v1.x) + (v2.x + v3.x);
        acc.y += (v0.y + v1.y) + (v2.y + v3.y);
        acc.z += (v0.z + v1.z) + (v2.z + v3.z);
        acc.w += (v0.w + v1.w) + (v2.w + v3.w);
    }
    for (; e < end; e++) {
        float4 v = hv[(size_t)csrc[e] * 32 + lane];
        acc.x += v.x; acc.y += v.y; acc.z += v.z; acc.w += v.w;
    }
    float dd = g_dinv[node];
    acc.x *= dd; acc.y *= dd; acc.z *= dd; acc.w *= dd;
    ((float4*)g_agg1)[(size_t)node * 32 + lane] = acc;
}

__global__ void k_agg64(int n) {
    const int lane16 = threadIdx.x & 15;
    const int half = threadIdx.x >> 4;
    int node = blockIdx.x * (blockDim.x >> 4) + half;
    if (node >= n) return;
    const float4* __restrict__ hv = (const float4*)g_h2;
    const int* __restrict__ csrc = g_csrc;

    float4 acc = hv[(size_t)node * 16 + lane16];
    int e = g_rowstart[node], end = g_rowstart[node + 1];
    for (; e + 4 <= end; e += 4) {
        int s0 = csrc[e], s1 = csrc[e + 1], s2 = csrc[e + 2], s3 = csrc[e + 3];
        float4 v0 = hv[(size_t)s0 * 16 + lane16];
        float4 v1 = hv[(size_t)s1 * 16 + lane16];
        float4 v2 = hv[(size_t)s2 * 16 + lane16];
        float4 v3 = hv[(size_t)s3 * 16 + lane16];
        acc.x += (v0.x + v1.x) + (v2.x + v3.x);
        acc.y += (v0.y + v1.y) + (v2.y + v3.y);
        acc.z += (v0.z + v1.z) + (v2.z + v3.z);
        acc.w += (v0.w + v1.w) + (v2.w + v3.w);
    }
    for (; e < end; e++) {
        float4 v = hv[(size_t)csrc[e] * 16 + lane16];
        acc.x += v.x; acc.y += v.y; acc.z += v.z; acc.w += v.w;
    }
    float dd = g_dinv[node];
    acc.x *= dd; acc.y *= dd; acc.z *= dd; acc.w *= dd;
    ((float4*)g_agg2)[(size_t)node * 16 + lane16] = acc;
}

// ---------------- final: (agg2+b2) @ W_eff + lin_b -> log_softmax ----------
__global__ void k_final(const float* __restrict__ b2, const float* __restrict__ linb,
                        float* __restrict__ out, int n) {
    __shared__ float W[C_OUT * C_OUT];
    for (int i = threadIdx.x; i < C_OUT * C_OUT; i += blockDim.x) W[i] = g_weff[i];
    __syncthreads();

    const int lane = threadIdx.x & 31;
    const int warp = threadIdx.x >> 5;
    const int nwarps = blockDim.x >> 5;
    int node = blockIdx.x * nwarps + warp;
    if (node >= n) return;

    const float* a = g_agg2 + (size_t)node * C_OUT;
    float acc0 = linb[lane];
    float acc1 = linb[lane + 32];
#pragma unroll
    for (int k = 0; k < C_OUT; k++) {
        float v = a[k] + b2[k];
        acc0 += v * W[k * C_OUT + lane];
        acc1 += v * W[k * C_OUT + lane + 32];
    }
    float m = fmaxf(acc0, acc1);
#pragma unroll
    for (int off = 16; off; off >>= 1) m = fmaxf(m, __shfl_xor_sync(0xffffffffu, m, off));
    float s = expf(acc0 - m) + expf(acc1 - m);
#pragma unroll
    for (int off = 16; off; off >>= 1) s += __shfl_xor_sync(0xffffffffu, s, off);
    float lse = m + logf(s);
    out[(size_t)node * C_OUT + lane]      = acc0 - lse;
    out[(size_t)node * C_OUT + lane + 32] = acc1 - lse;
}

// ---------------- launcher ----------------
extern "C" void kernel_launch(void* const* d_in, const int* in_sizes, int n_in,
                              void* d_out, int out_size) {
    const float* x    = (const float*)d_in[0];
    const void*  ei   = d_in[1];
    const float* W1   = (const float*)d_in[2];
    const float* b1   = (const float*)d_in[3];
    const float* W2   = (const float*)d_in[4];
    const float* b2   = (const float*)d_in[5];
    const float* linW = (const float*)d_in[6];
    const float* linb = (const float*)d_in[7];
    float* out = (float*)d_out;

    const int n = in_sizes[0] / C_IN;
    const int E = in_sizes[1] / 2;
    const int nb = (n + SCAN_TILE - 1) / SCAN_TILE;

    // setup + CSR build
    k_detect<<<1, 256>>>(ei, E, n);
    {
        int mx = n > C_OUT * C_OUT ? n : C_OUT * C_OUT;
        k_init<<<(mx + 255) / 256, 256>>>(linW, n);
    }
    k_deg_count<<<(E + 255) / 256, 256>>>(ei, E, n);
    k_scan1<<<nb, 256>>>(n);
    k_scan2<<<1, 256>>>(nb, n);
    k_scan3<<<nb, 256>>>(n);
    k_fill<<<(E + 255) / 256, 256>>>(ei, E, n);

    // layer 1: h1 = (x @ W1)*dinv ; agg1 = CSR-aggregate
    k_gemm_mma<C_HID, false><<<(n + 127) / 128, 256>>>(x, W1, nullptr, 0, 0, n);
    k_agg128<<<(n + 7) / 8, 256>>>(n);

    // layer 2: h2 = (relu(agg1+b1) @ W2)*dinv ; agg2 = CSR-aggregate
    k_gemm_mma<C_OUT, true><<<(n + 127) / 128, 256>>>(nullptr, W2, b1, 1, 1, n);
    k_agg64<<<(n + 15) / 16, 256>>>(n);

    // fused output: linear (folded concat) + log_softmax
    k_final<<<(n + 15) / 16, 512>>>(b2, linb, out, n);
}

// round 9
// speedup vs baseline: 4.3300x; 1.1222x over previous
#include <cuda_runtime.h>
#include <cuda_bf16.h>
#include <cstdint>

#define N_MAX  50000
#define E_MAX  1000000
#define C_IN   128
#define C_HID  128
#define C_OUT  64

#define SCAN_TILE 1024          // elements per scan block

// ---------------- scratch (device globals; no allocations) ----------------
__device__ __align__(16) float g_h1  [N_MAX * C_HID];   // x @ W1 (RAW, unscaled)
__device__ __align__(16) float g_agg1[N_MAX * C_HID];   // aggregated layer-1
__device__ __align__(16) float g_h2  [N_MAX * C_OUT];   // (relu(agg1+b1) @ W2) * dinv[row]
__device__ __align__(16) float g_agg2[N_MAX * C_OUT];   // aggregated layer-2
__device__ float g_dinv[N_MAX];
__device__ __align__(16) int g_indeg[N_MAX];   // edge in-degree (no self loop)
__device__ int   g_cursor[N_MAX];
__device__ __align__(16) int g_rowstart[N_MAX + 4];  // CSR (by dst) offsets
__device__ int   g_csrc[E_MAX];           // CSR src ids
__device__ int   g_bsum[(N_MAX + SCAN_TILE - 1) / SCAN_TILE + 1];
__device__ int   g_boff[(N_MAX + SCAN_TILE - 1) / SCAN_TILE + 1];
__device__ float g_weff[C_OUT * C_OUT];   // lin_W[0:64] + lin_W[64:128]
__device__ int   g_is32;                  // 1 if edge_index is int32

// ---------------- edge index fetch (dtype-agnostic) ----------------
__device__ __forceinline__ int edge_at(const void* ei, long long idx) {
    if (g_is32) return ((const int*)ei)[idx];
    return (int)(((const long long*)ei)[idx]);
}

// ---------------- dtype detector: int64 read out of range => int32 ----------
__global__ void k_detect(const void* __restrict__ ei, int E, int n) {
    __shared__ int bad;
    if (threadIdx.x == 0) bad = 0;
    __syncthreads();
    const long long* p = (const long long*)ei;
    int limit = E < 4096 ? E : 4096;
    for (int i = threadIdx.x; i < limit; i += blockDim.x) {
        long long v = p[i];
        if (v < 0 || v >= (long long)n) bad = 1;
    }
    __syncthreads();
    if (threadIdx.x == 0) g_is32 = bad;
}

// ---------------- init: zero counters + fold concat weights ----------------
__global__ void k_init(const float* __restrict__ linW, int n) {
    int i = blockIdx.x * blockDim.x + threadIdx.x;
    if (i < n) { g_indeg[i] = 0; g_cursor[i] = 0; }
    if (i < C_OUT * C_OUT) g_weff[i] = linW[i] + linW[i + C_OUT * C_OUT];
}

// 4 edges per thread (consecutive dsts share cachelines)
__global__ void k_deg_count(const void* __restrict__ ei, int E, int n) {
    int e0 = (blockIdx.x * blockDim.x + threadIdx.x) * 4;
    if (e0 >= E) return;
    int m = E - e0; if (m > 4) m = 4;
#pragma unroll
    for (int j = 0; j < 4; j++) {
        if (j >= m) break;
        int d = edge_at(ei, (long long)E + e0 + j);
        if ((unsigned)d < (unsigned)n) atomicAdd(&g_indeg[d], 1);
    }
}

// ---------------- 3-kernel grid scan over indeg -----------------------------
__global__ void k_scan1(int n) {
    __shared__ int wsum[8];
    __shared__ int woff[8];
    const int tid = threadIdx.x;
    const int lane = tid & 31, wid = tid >> 5;
    const int base = blockIdx.x * SCAN_TILE;
    const int i0 = base + tid * 4;

    int4 v = make_int4(0, 0, 0, 0);
    if (i0 + 3 < n) v = *(const int4*)&g_indeg[i0];
    else {
        if (i0 + 0 < n) v.x = g_indeg[i0 + 0];
        if (i0 + 1 < n) v.y = g_indeg[i0 + 1];
        if (i0 + 2 < n) v.z = g_indeg[i0 + 2];
        if (i0 + 3 < n) v.w = g_indeg[i0 + 3];
    }
    int tot = v.x + v.y + v.z + v.w;

    int inc = tot;
#pragma unroll
    for (int off = 1; off < 32; off <<= 1) {
        int o = __shfl_up_sync(0xffffffffu, inc, off);
        if (lane >= off) inc += o;
    }
    if (lane == 31) wsum[wid] = inc;
    __syncthreads();
    if (wid == 0) {
        int s = (lane < 8) ? wsum[lane] : 0;
#pragma unroll
        for (int off = 1; off < 8; off <<= 1) {
            int o = __shfl_up_sync(0xffffffffu, s, off);
            if (lane >= off) s += o;
        }
        if (lane < 8) woff[lane] = s - wsum[lane];
        if (lane == 7) g_bsum[blockIdx.x] = s;
    }
    __syncthreads();

    int excl = woff[wid] + (inc - tot);
    if (i0 + 0 < n) { g_rowstart[i0 + 0] = excl;                     g_dinv[i0 + 0] = rsqrtf((float)(v.x + 1)); }
    if (i0 + 1 < n) { g_rowstart[i0 + 1] = excl + v.x;               g_dinv[i0 + 1] = rsqrtf((float)(v.y + 1)); }
    if (i0 + 2 < n) { g_rowstart[i0 + 2] = excl + v.x + v.y;         g_dinv[i0 + 2] = rsqrtf((float)(v.z + 1)); }
    if (i0 + 3 < n) { g_rowstart[i0 + 3] = excl + v.x + v.y + v.z;   g_dinv[i0 + 3] = rsqrtf((float)(v.w + 1)); }
}

__global__ void k_scan2(int nb, int n) {
    __shared__ int s[256];
    const int tid = threadIdx.x;
    s[tid] = (tid < nb) ? g_bsum[tid] : 0;
    __syncthreads();
    for (int off = 1; off < 256; off <<= 1) {
        int v = (tid >= off) ? s[tid - off] : 0;
        __syncthreads();
        s[tid] += v;
        __syncthreads();
    }
    if (tid < nb) g_boff[tid] = tid ? s[tid - 1] : 0;
    if (tid == 255) g_rowstart[n] = s[255];
}

__global__ void k_scan3(int n) {
    int off = g_boff[blockIdx.x];
    int i0 = blockIdx.x * SCAN_TILE + threadIdx.x * 4;
    if (i0 + 3 < n) {
        int4 r = *(const int4*)&g_rowstart[i0];
        r.x += off; r.y += off; r.z += off; r.w += off;
        *(int4*)&g_rowstart[i0] = r;
    } else {
        for (int j = 0; j < 4 && i0 + j < n; j++) g_rowstart[i0 + j] += off;
    }
}

// ---------------- CSR fill (counting-sort scatter of src ids) --------------
__global__ void k_fill(const void* __restrict__ ei, int E, int n) {
    int e = blockIdx.x * blockDim.x + threadIdx.x;
    if (e >= E) return;
    int s = edge_at(ei, e);
    int d = edge_at(ei, (long long)E + e);
    if ((unsigned)s >= (unsigned)n || (unsigned)d >= (unsigned)n) return;
    int pos = atomicAdd(&g_cursor[d], 1);
    int idx = g_rowstart[d] + pos;
    if (idx < E_MAX) g_csrc[idx] = s;
}

// ============ bf16x3 tensor-core GEMM via mma.sync (m16n8k16) ==============
// C[M,N] = (op A[M,128]) @ B[128,N]; optional epilogue dinv row scale.
__device__ __forceinline__ uint32_t pack_hi(float x, float y) {
    __nv_bfloat16 a = __float2bfloat16(x), b = __float2bfloat16(y);
    return ((uint32_t)__bfloat16_as_ushort(b) << 16) | __bfloat16_as_ushort(a);
}
__device__ __forceinline__ uint32_t pack_lo(float x, float y) {
    __nv_bfloat16 a = __float2bfloat16(x), b = __float2bfloat16(y);
    float rx = x - __bfloat162float(a), ry = y - __bfloat162float(b);
    __nv_bfloat16 c = __float2bfloat16(rx), d = __float2bfloat16(ry);
    return ((uint32_t)__bfloat16_as_ushort(d) << 16) | __bfloat16_as_ushort(c);
}

__device__ __forceinline__ void mma_bf16(float* d, uint32_t a0, uint32_t a1,
                                         uint32_t a2, uint32_t a3,
                                         uint32_t b0, uint32_t b1) {
    asm volatile(
        "mma.sync.aligned.m16n8k16.row.col.f32.bf16.bf16.f32 "
        "{%0,%1,%2,%3}, {%4,%5,%6,%7}, {%8,%9}, {%0,%1,%2,%3};"
        : "+f"(d[0]), "+f"(d[1]), "+f"(d[2]), "+f"(d[3])
        : "r"(a0), "r"(a1), "r"(a2), "r"(a3), "r"(b0), "r"(b1));
}

template <int N, bool RELU_BIAS, bool SCALE>
__global__ void __launch_bounds__(256)
k_gemm_mma(const float* __restrict__ Ain, const float* __restrict__ Bg,
           const float* __restrict__ bias, int a_from_agg1, int c_sel, int M) {
    constexpr int LD = N + 8;
    constexpr int NT = N / 8;
    __shared__ uint32_t sBh[32][LD];
    __shared__ uint32_t sBl[32][LD];

    const float* A = a_from_agg1 ? g_agg1 : Ain;
    float* C = c_sel ? g_h2 : g_h1;

    const int tid = threadIdx.x;
    const int warp = tid >> 5, lane = tid & 31;
    const int g = lane >> 2, q = lane & 3;
    const int row0 = blockIdx.x * 128 + warp * 16 + g;
    const int row1 = row0 + 8;
    const bool v0 = row0 < M, v1 = row1 < M;

    float acc[NT][4];
#pragma unroll
    for (int c = 0; c < NT; c++)
#pragma unroll
        for (int i = 0; i < 4; i++) acc[c][i] = 0.f;

    const float* ar0 = A + (size_t)row0 * 128;
    const float* ar1 = A + (size_t)row1 * 128;

    for (int half = 0; half < 2; half++) {
        __syncthreads();
        for (int idx = tid; idx < 64 * N; idx += 256) {
            int k = idx / N;
            int nn = idx - k * N;
            float v = Bg[(size_t)(half * 64 + k) * N + nn];
            __nv_bfloat16 hi = __float2bfloat16(v);
            __nv_bfloat16 lo = __float2bfloat16(v - __bfloat162float(hi));
            ((unsigned short*)&sBh[k >> 1][nn])[k & 1] = __bfloat16_as_ushort(hi);
            ((unsigned short*)&sBl[k >> 1][nn])[k & 1] = __bfloat16_as_ushort(lo);
        }
        __syncthreads();

#pragma unroll
        for (int j = 0; j < 4; j++) {
            const int kb = half * 64 + j * 16;
            float2 p00 = make_float2(0.f, 0.f), p01 = p00, p10 = p00, p11 = p00;
            if (v0) { p00 = *(const float2*)(ar0 + kb + 2 * q);
                      p01 = *(const float2*)(ar0 + kb + 2 * q + 8); }
            if (v1) { p10 = *(const float2*)(ar1 + kb + 2 * q);
                      p11 = *(const float2*)(ar1 + kb + 2 * q + 8); }
            if (RELU_BIAS) {
                float2 bA = *(const float2*)(bias + kb + 2 * q);
                float2 bB = *(const float2*)(bias + kb + 2 * q + 8);
                p00.x = fmaxf(p00.x + bA.x, 0.f); p00.y = fmaxf(p00.y + bA.y, 0.f);
                p01.x = fmaxf(p01.x + bB.x, 0.f); p01.y = fmaxf(p01.y + bB.y, 0.f);
                p10.x = fmaxf(p10.x + bA.x, 0.f); p10.y = fmaxf(p10.y + bA.y, 0.f);
                p11.x = fmaxf(p11.x + bB.x, 0.f); p11.y = fmaxf(p11.y + bB.y, 0.f);
            }
            uint32_t ah0 = pack_hi(p00.x, p00.y), al0 = pack_lo(p00.x, p00.y);
            uint32_t ah1 = pack_hi(p10.x, p10.y), al1 = pack_lo(p10.x, p10.y);
            uint32_t ah2 = pack_hi(p01.x, p01.y), al2 = pack_lo(p01.x, p01.y);
            uint32_t ah3 = pack_hi(p11.x, p11.y), al3 = pack_lo(p11.x, p11.y);

            const int kp0 = j * 8 + q, kp1 = kp0 + 4;
#pragma unroll
            for (int c = 0; c < NT; c++) {
                int nn = c * 8 + g;
                uint32_t b0h = sBh[kp0][nn];
                uint32_t b1h = sBh[kp1][nn];
                uint32_t b0l = sBl[kp0][nn];
                uint32_t b1l = sBl[kp1][nn];
                mma_bf16(acc[c], ah0, ah1, ah2, ah3, b0h, b1h);
                mma_bf16(acc[c], ah0, ah1, ah2, ah3, b0l, b1l);
                mma_bf16(acc[c], al0, al1, al2, al3, b0h, b1h);
            }
        }
    }

    float s0 = 1.f, s1 = 1.f;
    if (SCALE) {
        s0 = v0 ? g_dinv[row0] : 0.f;
        s1 = v1 ? g_dinv[row1] : 0.f;
    }
#pragma unroll
    for (int c = 0; c < NT; c++) {
        int col = c * 8 + 2 * q;
        if (v0) *(float2*)(C + (size_t)row0 * N + col) =
            make_float2(acc[c][0] * s0, acc[c][1] * s0);
        if (v1) *(float2*)(C + (size_t)row1 * N + col) =
            make_float2(acc[c][2] * s1, acc[c][3] * s1);
    }
}

// ---------------- CSR aggregation (no atomics) -----------------------------
// h1 is RAW; agg1[d] = dinv[d]*(dinv[d]*h1[d] + sum_e dinv[s]*h1[s]).
__global__ void k_agg128(int n) {
    const int lane = threadIdx.x & 31;
    const int warp = threadIdx.x >> 5;
    int node = blockIdx.x * (blockDim.x >> 5) + warp;
    if (node >= n) return;
    const float4* __restrict__ hv = (const float4*)g_h1;
    const int* __restrict__ csrc = g_csrc;
    const float* __restrict__ dinv = g_dinv;

    float dd = dinv[node];
    float4 self = hv[(size_t)node * 32 + lane];
    float4 acc;
    acc.x = self.x * dd; acc.y = self.y * dd;
    acc.z = self.z * dd; acc.w = self.w * dd;

    int e = g_rowstart[node], end = g_rowstart[node + 1];
    for (; e + 4 <= end; e += 4) {
        int s0 = csrc[e], s1 = csrc[e + 1], s2 = csrc[e + 2], s3 = csrc[e + 3];
        float c0 = dinv[s0], c1 = dinv[s1], c2 = dinv[s2], c3 = dinv[s3];
        float4 v0 = hv[(size_t)s0 * 32 + lane];
        float4 v1 = hv[(size_t)s1 * 32 + lane];
        float4 v2 = hv[(size_t)s2 * 32 + lane];
        float4 v3 = hv[(size_t)s3 * 32 + lane];
        acc.x += v0.x * c0 + v1.x * c1 + v2.x * c2 + v3.x * c3;
        acc.y += v0.y * c0 + v1.y * c1 + v2.y * c2 + v3.y * c3;
        acc.z += v0.z * c0 + v1.z * c1 + v2.z * c2 + v3.z * c3;
        acc.w += v0.w * c0 + v1.w * c1 + v2.w * c2 + v3.w * c3;
    }
    for (; e < end; e++) {
        int s0 = csrc[e];
        float c0 = dinv[s0];
        float4 v = hv[(size_t)s0 * 32 + lane];
        acc.x += v.x * c0; acc.y += v.y * c0;
        acc.z += v.z * c0; acc.w += v.w * c0;
    }
    acc.x *= dd; acc.y *= dd; acc.z *= dd; acc.w *= dd;
    ((float4*)g_agg1)[(size_t)node * 32 + lane] = acc;
}

// h2 pre-scaled by dinv; agg2[d] = dinv[d]*(h2[d] + sum_e h2[s]).
__global__ void k_agg64(int n) {
    const int lane16 = threadIdx.x & 15;
    const int half = threadIdx.x >> 4;
    int node = blockIdx.x * (blockDim.x >> 4) + half;
    if (node >= n) return;
    const float4* __restrict__ hv = (const float4*)g_h2;
    const int* __restrict__ csrc = g_csrc;

    float4 acc = hv[(size_t)node * 16 + lane16];
    int e = g_rowstart[node], end = g_rowstart[node + 1];
    for (; e + 4 <= end; e += 4) {
        int s0 = csrc[e], s1 = csrc[e + 1], s2 = csrc[e + 2], s3 = csrc[e + 3];
        float4 v0 = hv[(size_t)s0 * 16 + lane16];
        float4 v1 = hv[(size_t)s1 * 16 + lane16];
        float4 v2 = hv[(size_t)s2 * 16 + lane16];
        float4 v3 = hv[(size_t)s3 * 16 + lane16];
        acc.x += (v0.x + v1.x) + (v2.x + v3.x);
        acc.y += (v0.y + v1.y) + (v2.y + v3.y);
        acc.z += (v0.z + v1.z) + (v2.z + v3.z);
        acc.w += (v0.w + v1.w) + (v2.w + v3.w);
    }
    for (; e < end; e++) {
        float4 v = hv[(size_t)csrc[e] * 16 + lane16];
        acc.x += v.x; acc.y += v.y; acc.z += v.z; acc.w += v.w;
    }
    float dd = g_dinv[node];
    acc.x *= dd; acc.y *= dd; acc.z *= dd; acc.w *= dd;
    ((float4*)g_agg2)[(size_t)node * 16 + lane16] = acc;
}

// ---------------- final: (agg2+b2) @ W_eff + lin_b -> log_softmax ----------
__global__ void k_final(const float* __restrict__ b2, const float* __restrict__ linb,
                        float* __restrict__ out, int n) {
    __shared__ float W[C_OUT * C_OUT];
    for (int i = threadIdx.x; i < C_OUT * C_OUT; i += blockDim.x) W[i] = g_weff[i];
    __syncthreads();

    const int lane = threadIdx.x & 31;
    const int warp = threadIdx.x >> 5;
    const int nwarps = blockDim.x >> 5;
    int node = blockIdx.x * nwarps + warp;
    if (node >= n) return;

    const float* a = g_agg2 + (size_t)node * C_OUT;
    float acc0 = linb[lane];
    float acc1 = linb[lane + 32];
#pragma unroll
    for (int k = 0; k < C_OUT; k++) {
        float v = a[k] + b2[k];
        acc0 += v * W[k * C_OUT + lane];
        acc1 += v * W[k * C_OUT + lane + 32];
    }
    float m = fmaxf(acc0, acc1);
#pragma unroll
    for (int off = 16; off; off >>= 1) m = fmaxf(m, __shfl_xor_sync(0xffffffffu, m, off));
    float s = expf(acc0 - m) + expf(acc1 - m);
#pragma unroll
    for (int off = 16; off; off >>= 1) s += __shfl_xor_sync(0xffffffffu, s, off);
    float lse = m + logf(s);
    out[(size_t)node * C_OUT + lane]      = acc0 - lse;
    out[(size_t)node * C_OUT + lane + 32] = acc1 - lse;
}

// ---------------- launcher (fork-join graph: gemm1 || CSR build) -----------
extern "C" void kernel_launch(void* const* d_in, const int* in_sizes, int n_in,
                              void* d_out, int out_size) {
    const float* x    = (const float*)d_in[0];
    const void*  ei   = d_in[1];
    const float* W1   = (const float*)d_in[2];
    const float* b1   = (const float*)d_in[3];
    const float* W2   = (const float*)d_in[4];
    const float* b2   = (const float*)d_in[5];
    const float* linW = (const float*)d_in[6];
    const float* linb = (const float*)d_in[7];
    float* out = (float*)d_out;

    const int n = in_sizes[0] / C_IN;
    const int E = in_sizes[1] / 2;
    const int nb = (n + SCAN_TILE - 1) / SCAN_TILE;

    cudaStream_t s2;
    cudaEvent_t evFork, evJoin;
    cudaStreamCreateWithFlags(&s2, cudaStreamNonBlocking);
    cudaEventCreateWithFlags(&evFork, cudaEventDisableTiming);
    cudaEventCreateWithFlags(&evJoin, cudaEventDisableTiming);

    // ---- fork: gemm1 (raw h1, no dinv dependency) runs on s2
    cudaEventRecord(evFork, 0);
    cudaStreamWaitEvent(s2, evFork, 0);
    k_gemm_mma<C_HID, false, false><<<(n + 127) / 128, 256, 0, s2>>>(
        x, W1, nullptr, 0, 0, n);
    cudaEventRecord(evJoin, s2);

    // ---- main stream: CSR build chain
    k_detect<<<1, 256>>>(ei, E, n);
    {
        int mx = n > C_OUT * C_OUT ? n : C_OUT * C_OUT;
        k_init<<<(mx + 255) / 256, 256>>>(linW, n);
    }
    k_deg_count<<<(E / 4 + 256) / 256, 256>>>(ei, E, n);
    k_scan1<<<nb, 256>>>(n);
    k_scan2<<<1, 256>>>(nb, n);
    k_scan3<<<nb, 256>>>(n);
    k_fill<<<(E + 255) / 256, 256>>>(ei, E, n);

    // ---- join: aggregation needs h1 + CSR + dinv
    cudaStreamWaitEvent(0, evJoin, 0);
    k_agg128<<<(n + 7) / 8, 256>>>(n);

    // layer 2: h2 = (relu(agg1+b1) @ W2)*dinv ; agg2 = CSR-aggregate
    k_gemm_mma<C_OUT, true, true><<<(n + 127) / 128, 256>>>(nullptr, W2, b1, 1, 1, n);
    k_agg64<<<(n + 15) / 16, 256>>>(n);

    // fused output: linear (folded concat) + log_softmax
    k_final<<<(n + 15) / 16, 512>>>(b2, linb, out, n);

    cudaEventDestroy(evFork);
    cudaEventDestroy(evJoin);
    cudaStreamDestroy(s2);
}